// round 10
// baseline (speedup 1.0000x reference)
#include <cuda_runtime.h>
#include <cstdint>

// Problem dimensions (fixed by the reference)
#define PN0 200000
#define PN1 50000
#define PN2 10000
#define PD_IN 128
#define PD_PROMPT 64
#define PD_CAT 192
#define PD_HID 256
#define PE0 800000
#define PE1 160000

// ---------------------------------------------------------------------------
// Scratch (device globals; no allocations allowed)
// ---------------------------------------------------------------------------
__device__ float g_hp[(size_t)PN0 * PD_PROMPT];  // selected prompt (relu'd)
__device__ float g_agg0[(size_t)PN1 * PD_CAT];   // mean-agg of [F|hp]
__device__ float g_h1[(size_t)PN1 * PD_HID];
__device__ float g_agg1[(size_t)PN2 * PD_HID];
__device__ float g_h2[(size_t)PN2 * PD_HID];
__device__ int g_cnt0[PN1], g_fill0[PN1], g_rowptr0[PN1 + 1];
__device__ int g_cnt1[PN2], g_fill1[PN2], g_rowptr1[PN2 + 1];
__device__ int g_csr0[PE0], g_csr1[PE1];

// ---------------------------------------------------------------------------
// Streams/events for graph-capturable fork/join. Created at static-init time
// (before the harness's memory checkpoints) and reused every call.
// ---------------------------------------------------------------------------
struct ExecRes {
    cudaStream_t s1, s2;
    cudaEvent_t ev_start, ev_start2, ev_csr, ev_hp, ev_aggF, ev_self0, ev_h1, ev_self1;
    ExecRes() {
        cudaStreamCreateWithFlags(&s1, cudaStreamNonBlocking);
        cudaStreamCreateWithFlags(&s2, cudaStreamNonBlocking);
        cudaEventCreateWithFlags(&ev_start, cudaEventDisableTiming);
        cudaEventCreateWithFlags(&ev_start2, cudaEventDisableTiming);
        cudaEventCreateWithFlags(&ev_csr, cudaEventDisableTiming);
        cudaEventCreateWithFlags(&ev_hp, cudaEventDisableTiming);
        cudaEventCreateWithFlags(&ev_aggF, cudaEventDisableTiming);
        cudaEventCreateWithFlags(&ev_self0, cudaEventDisableTiming);
        cudaEventCreateWithFlags(&ev_h1, cudaEventDisableTiming);
        cudaEventCreateWithFlags(&ev_self1, cudaEventDisableTiming);
    }
};
static ExecRes g_res;

// ---------------------------------------------------------------------------
// tf32 helpers
// ---------------------------------------------------------------------------
__device__ __forceinline__ uint32_t f2tf(float f) {
    uint32_t u;
    asm("cvt.rna.tf32.f32 %0, %1;" : "=r"(u) : "f"(f));
    return u;
}

__device__ __forceinline__ void mma_tf32(float& c0, float& c1, float& c2, float& c3,
                                         uint32_t a0, uint32_t a1, uint32_t a2, uint32_t a3,
                                         uint32_t b0, uint32_t b1) {
    asm volatile(
        "mma.sync.aligned.m16n8k8.row.col.f32.tf32.tf32.f32 "
        "{%0,%1,%2,%3}, {%4,%5,%6,%7}, {%8,%9}, {%0,%1,%2,%3};"
        : "+f"(c0), "+f"(c1), "+f"(c2), "+f"(c3)
        : "r"(a0), "r"(a1), "r"(a2), "r"(a3), "r"(b0), "r"(b1));
}

// ---------------------------------------------------------------------------
// Zero 4 int arrays in one launch
// ---------------------------------------------------------------------------
__global__ void zero4_kernel(int* a, int na, int* b, int nb, int* c, int nc, int* d, int nd) {
    int i = blockIdx.x * blockDim.x + threadIdx.x;
    if (i < na) a[i] = 0;
    if (i < nb) b[i] = 0;
    if (i < nc) c[i] = 0;
    if (i < nd) d[i] = 0;
}

// ---------------------------------------------------------------------------
// Fused histogram over both edge sets
// ---------------------------------------------------------------------------
__global__ void hist2_kernel(const int* __restrict__ dst0, int E0, int* __restrict__ cnt0,
                             const int* __restrict__ dst1, int E1, int* __restrict__ cnt1) {
    int i = blockIdx.x * blockDim.x + threadIdx.x;
    if (i < E0) atomicAdd(&cnt0[dst0[i]], 1);
    if (i < E1) atomicAdd(&cnt1[dst1[i]], 1);
}

// ---------------------------------------------------------------------------
// Single-block exclusive scan (warp-shuffle, 4/thread); 2 arrays in one launch
// ---------------------------------------------------------------------------
__device__ void scan_body(const int* __restrict__ cnt, int* __restrict__ rowptr, int n) {
    __shared__ int warp_sums[32];
    __shared__ int s_carry;
    const int tid = threadIdx.x;
    const int lane = tid & 31;
    const int warp = tid >> 5;
    if (tid == 0) { s_carry = 0; rowptr[0] = 0; }
    __syncthreads();

    const int TILE = 4096;  // 1024 threads * 4
    for (int base = 0; base < n; base += TILE) {
        int i0 = base + tid * 4;
        int4 v = make_int4(0, 0, 0, 0);
        if (i0 + 3 < n) {
            v = *(const int4*)(cnt + i0);
        } else {
            if (i0 + 0 < n) v.x = cnt[i0 + 0];
            if (i0 + 1 < n) v.y = cnt[i0 + 1];
            if (i0 + 2 < n) v.z = cnt[i0 + 2];
        }
        int s1 = v.x, s2 = s1 + v.y, s3 = s2 + v.z, s4 = s3 + v.w;
        int t = s4;
#pragma unroll
        for (int off = 1; off < 32; off <<= 1) {
            int u = __shfl_up_sync(0xFFFFFFFFu, t, off);
            if (lane >= off) t += u;
        }
        if (lane == 31) warp_sums[warp] = t;
        __syncthreads();
        if (warp == 0) {
            int w = warp_sums[lane];
            int tw = w;
#pragma unroll
            for (int off = 1; off < 32; off <<= 1) {
                int u = __shfl_up_sync(0xFFFFFFFFu, tw, off);
                if (lane >= off) tw += u;
            }
            warp_sums[lane] = tw - w;  // exclusive
        }
        __syncthreads();
        int excl = s_carry + warp_sums[warp] + (t - s4);
        if (i0 + 0 < n) rowptr[i0 + 1] = excl + s1;
        if (i0 + 1 < n) rowptr[i0 + 2] = excl + s2;
        if (i0 + 2 < n) rowptr[i0 + 3] = excl + s3;
        if (i0 + 3 < n) rowptr[i0 + 4] = excl + s4;
        __syncthreads();
        if (tid == 1023) s_carry = excl + s4;
        // next-iteration __syncthreads orders this write before reads
    }
}

__global__ void scan2_kernel(const int* c0, int* r0, int n0,
                             const int* c1, int* r1, int n1) {
    if (blockIdx.x == 0) scan_body(c0, r0, n0);
    else scan_body(c1, r1, n1);
}

// ---------------------------------------------------------------------------
// Fused scatter over both edge sets
// ---------------------------------------------------------------------------
__global__ void scatter2_kernel(const int* __restrict__ src0, const int* __restrict__ dst0, int E0,
                                const int* __restrict__ rowptr0, int* __restrict__ fill0,
                                int* __restrict__ csr0,
                                const int* __restrict__ src1, const int* __restrict__ dst1, int E1,
                                const int* __restrict__ rowptr1, int* __restrict__ fill1,
                                int* __restrict__ csr1) {
    int i = blockIdx.x * blockDim.x + threadIdx.x;
    if (i < E0) {
        int d = dst0[i];
        int pos = rowptr0[d] + atomicAdd(&fill0[d], 1);
        csr0[pos] = src0[i];
    }
    if (i < E1) {
        int d = dst1[i];
        int pos = rowptr1[d] + atomicAdd(&fill1[d], 1);
        csr1[pos] = src1[i];
    }
}

// ---------------------------------------------------------------------------
// tf32 tensor-core GEMM: BM=128, BN=128, BK=32, 256 threads (8 warps 2x4),
// warp tile 64x32, mma.sync.m16n8k8. A row-major, B row-major [K,N].
// Register-staged double buffering: prefetch next tile while computing.
// smem: As[m][k] stride 36 (bank = 4m+k), Bs[k][n] stride 136 (bank = 8k+n).
// ---------------------------------------------------------------------------
#define TBM 128
#define TBN 128
#define TBK 32
#define AS_STRIDE 36
#define BS_STRIDE 136

#define SEG_RESOLVE(kt, Aout, Bout, kload, lda)                                 \
    if ((kt) < K1) { Aout = A1; Bout = B1; kload = (kt); lda = K1; }            \
    else if ((kt) < K1 + K2) { Aout = A2; Bout = B2; kload = (kt) - K1; lda = K2; } \
    else { Aout = A3; Bout = B3; kload = (kt) - K1 - K2; lda = K3; }

#define LOAD_REGS(kt, ra, rb)                                                   \
    {                                                                           \
        const float *A_, *B_; int kload_, lda_;                                 \
        SEG_RESOLVE(kt, A_, B_, kload_, lda_);                                  \
        _Pragma("unroll")                                                       \
        for (int i = 0; i < 4; i++) {                                           \
            int idx = tid + i * 256;                                            \
            int m = idx >> 3, kq = (idx & 7) * 4;                               \
            int grow = block_row + m;                                           \
            ra[i] = make_float4(0.f, 0.f, 0.f, 0.f);                            \
            if (grow < M)                                                       \
                ra[i] = *(const float4*)(A_ + (size_t)grow * lda_ + kload_ + kq); \
        }                                                                       \
        _Pragma("unroll")                                                       \
        for (int i = 0; i < 4; i++) {                                           \
            int idx = tid + i * 256;                                            \
            int k = idx >> 5, n4 = (idx & 31) * 4;                              \
            rb[i] = *(const float4*)(B_ + (size_t)(kload_ + k) * N + block_col + n4); \
        }                                                                       \
    }

#define STORE_TILES(ra, rb)                                                     \
    {                                                                           \
        _Pragma("unroll")                                                       \
        for (int i = 0; i < 4; i++) {                                           \
            int idx = tid + i * 256;                                            \
            int m = idx >> 3, kq = (idx & 7) * 4;                               \
            uint4 u = make_uint4(f2tf(ra[i].x), f2tf(ra[i].y),                  \
                                 f2tf(ra[i].z), f2tf(ra[i].w));                 \
            *(uint4*)&As[m][kq] = u;                                            \
        }                                                                       \
        _Pragma("unroll")                                                       \
        for (int i = 0; i < 4; i++) {                                           \
            int idx = tid + i * 256;                                            \
            int k = idx >> 5, n4 = (idx & 31) * 4;                              \
            uint4 u = make_uint4(f2tf(rb[i].x), f2tf(rb[i].y),                  \
                                 f2tf(rb[i].z), f2tf(rb[i].w));                 \
            *(uint4*)&Bs[k][n4] = u;                                            \
        }                                                                       \
    }

#define T_COMPUTE()                                                             \
    {                                                                           \
        _Pragma("unroll")                                                       \
        for (int ks = 0; ks < 4; ks++) {                                        \
            uint32_t af[4][4], bf[4][2];                                        \
            _Pragma("unroll")                                                   \
            for (int mt = 0; mt < 4; mt++) {                                    \
                int mb = warpM + 16 * mt + qr;                                  \
                int kb = 8 * ks + qc;                                           \
                af[mt][0] = As[mb][kb];                                         \
                af[mt][1] = As[mb + 8][kb];                                     \
                af[mt][2] = As[mb][kb + 4];                                     \
                af[mt][3] = As[mb + 8][kb + 4];                                 \
            }                                                                   \
            _Pragma("unroll")                                                   \
            for (int nt = 0; nt < 4; nt++) {                                    \
                int nb = warpN + 8 * nt + qr;                                   \
                int kb = 8 * ks + qc;                                           \
                bf[nt][0] = Bs[kb][nb];                                         \
                bf[nt][1] = Bs[kb + 4][nb];                                     \
            }                                                                   \
            _Pragma("unroll")                                                   \
            for (int mt = 0; mt < 4; mt++)                                      \
                _Pragma("unroll")                                               \
                for (int nt = 0; nt < 4; nt++)                                  \
                    mma_tf32(acc[mt][nt][0], acc[mt][nt][1],                    \
                             acc[mt][nt][2], acc[mt][nt][3],                    \
                             af[mt][0], af[mt][1], af[mt][2], af[mt][3],        \
                             bf[nt][0], bf[nt][1]);                             \
        }                                                                       \
    }

#define T_PROLOG()                                                              \
    const int tid = threadIdx.x;                                                \
    const int wid = tid >> 5;                                                   \
    const int lane = tid & 31;                                                  \
    const int qr = lane >> 2;                                                   \
    const int qc = lane & 3;                                                    \
    const int warpM = (wid & 1) * 64;                                           \
    const int warpN = (wid >> 1) * 32;                                          \
    float acc[4][4][4];                                                         \
    _Pragma("unroll")                                                           \
    for (int a = 0; a < 4; a++)                                                 \
        _Pragma("unroll")                                                       \
        for (int b = 0; b < 4; b++)                                             \
            _Pragma("unroll")                                                   \
            for (int c = 0; c < 4; c++) acc[a][b][c] = 0.0f;

// Triple-K-segment GEMM: C = [A1|A2|A3] @ [B1;B2;B3] (+bias) (+C) (relu).
// flags: bit0 = relu, bit1 = addC (accumulate into existing C contents).
// K1,K2,K3 multiples of 32 (K2/K3 may be 0). N multiple of 128.
__global__ __launch_bounds__(256)
void gemm3_tf32_kernel(const float* __restrict__ A1, const float* __restrict__ B1, int K1,
                       const float* __restrict__ A2, const float* __restrict__ B2, int K2,
                       const float* __restrict__ A3, const float* __restrict__ B3, int K3,
                       const float* __restrict__ bias, float* __restrict__ C,
                       int M, int N, int flags) {
    __shared__ uint32_t As[TBM][AS_STRIDE];
    __shared__ uint32_t Bs[TBK][BS_STRIDE];
    const int block_row = blockIdx.y * TBM;
    const int block_col = blockIdx.x * TBN;
    T_PROLOG();

    const int Ktot = K1 + K2 + K3;
    float4 ra[4], rb[4];
    LOAD_REGS(0, ra, rb);
    for (int kt = 0; kt < Ktot; kt += TBK) {
        STORE_TILES(ra, rb);
        __syncthreads();
        float4 na[4], nb[4];
        if (kt + TBK < Ktot) {
            LOAD_REGS(kt + TBK, na, nb);
        }
        T_COMPUTE();
        __syncthreads();
#pragma unroll
        for (int i = 0; i < 4; i++) { ra[i] = na[i]; rb[i] = nb[i]; }
    }

    const bool doRelu = (flags & 1) != 0;
    const bool doAdd = (flags & 2) != 0;
#pragma unroll
    for (int mt = 0; mt < 4; mt++) {
        int r0 = block_row + warpM + 16 * mt + qr;
        int r1 = r0 + 8;
#pragma unroll
        for (int nt = 0; nt < 4; nt++) {
            int col = block_col + warpN + 8 * nt + 2 * qc;
            float bx = 0.f, by = 0.f;
            if (bias) { bx = bias[col]; by = bias[col + 1]; }
            float v0 = acc[mt][nt][0] + bx, v1 = acc[mt][nt][1] + by;
            float v2 = acc[mt][nt][2] + bx, v3 = acc[mt][nt][3] + by;
            if (r0 < M) {
                if (doAdd) {
                    float2 c = *(const float2*)(C + (size_t)r0 * N + col);
                    v0 += c.x; v1 += c.y;
                }
                if (doRelu) { v0 = fmaxf(v0, 0.f); v1 = fmaxf(v1, 0.f); }
                *(float2*)(C + (size_t)r0 * N + col) = make_float2(v0, v1);
            }
            if (r1 < M) {
                if (doAdd) {
                    float2 c = *(const float2*)(C + (size_t)r1 * N + col);
                    v2 += c.x; v3 += c.y;
                }
                if (doRelu) { v2 = fmaxf(v2, 0.f); v3 = fmaxf(v3, 0.f); }
                *(float2*)(C + (size_t)r1 * N + col) = make_float2(v2, v3);
            }
        }
    }
}

// Prompt GEMM: P = F @ [w_pin | w_pout] (N=128), register double-buffered.
// Epilogue selects per-row by mask, adds bias, relu, writes hp[N0 x 64].
__global__ __launch_bounds__(256)
void prompt_gemm_tf32_kernel(const float* __restrict__ F,
                             const float* __restrict__ w_pin, const float* __restrict__ w_pout,
                             const int* __restrict__ mask,
                             const float* __restrict__ b_pin, const float* __restrict__ b_pout,
                             float* __restrict__ hp, int M) {
    __shared__ uint32_t As[TBM][AS_STRIDE];
    __shared__ uint32_t Bs[TBK][BS_STRIDE];
    const int block_row = blockIdx.y * TBM;
    T_PROLOG();

#define P_LOAD(kt, ra, rb)                                                      \
    {                                                                           \
        _Pragma("unroll")                                                       \
        for (int i = 0; i < 4; i++) {                                           \
            int idx = tid + i * 256;                                            \
            int m = idx >> 3, kq = (idx & 7) * 4;                               \
            int grow = block_row + m;                                           \
            ra[i] = make_float4(0.f, 0.f, 0.f, 0.f);                            \
            if (grow < M)                                                       \
                ra[i] = *(const float4*)(F + (size_t)grow * PD_IN + (kt) + kq); \
        }                                                                       \
        _Pragma("unroll")                                                       \
        for (int i = 0; i < 4; i++) {                                           \
            int idx = tid + i * 256;                                            \
            int k = idx >> 5, n4 = (idx & 31) * 4;                              \
            const float* src = (n4 < 64)                                        \
                ? (w_pin + (size_t)((kt) + k) * PD_PROMPT + n4)                 \
                : (w_pout + (size_t)((kt) + k) * PD_PROMPT + (n4 - 64));        \
            rb[i] = *(const float4*)src;                                        \
        }                                                                       \
    }

    float4 ra[4], rb[4];
    P_LOAD(0, ra, rb);
    for (int kt = 0; kt < PD_IN; kt += TBK) {
        STORE_TILES(ra, rb);
        __syncthreads();
        float4 na[4], nb[4];
        if (kt + TBK < PD_IN) {
            P_LOAD(kt + TBK, na, nb);
        }
        T_COMPUTE();
        __syncthreads();
#pragma unroll
        for (int i = 0; i < 4; i++) { ra[i] = na[i]; rb[i] = nb[i]; }
    }

#pragma unroll
    for (int mt = 0; mt < 4; mt++) {
        int r0 = block_row + warpM + 16 * mt + qr;
        int r1 = r0 + 8;
        bool m0 = (r0 < M) && (mask[r0 < M ? r0 : 0] != 0);
        bool m1 = (r1 < M) && (mask[r1 < M ? r1 : 0] != 0);
#pragma unroll
        for (int nt = 0; nt < 4; nt++) {
            int col = warpN + 8 * nt + 2 * qc;  // 0..126, pair within one half
            bool isIn = col < 64;
            int dcol = isIn ? col : col - 64;
            float bx = isIn ? b_pin[dcol] : b_pout[dcol];
            float by = isIn ? b_pin[dcol + 1] : b_pout[dcol + 1];
            if (r0 < M && (isIn == m0)) {
                float2 o = make_float2(fmaxf(acc[mt][nt][0] + bx, 0.f),
                                       fmaxf(acc[mt][nt][1] + by, 0.f));
                *(float2*)(hp + (size_t)r0 * PD_PROMPT + dcol) = o;
            }
            if (r1 < M && (isIn == m1)) {
                float2 o = make_float2(fmaxf(acc[mt][nt][2] + bx, 0.f),
                                       fmaxf(acc[mt][nt][3] + by, 0.f));
                *(float2*)(hp + (size_t)r1 * PD_PROMPT + dcol) = o;
            }
        }
    }
#undef P_LOAD
}

// ---------------------------------------------------------------------------
// Mean aggregation of F columns into agg0[:, 0:128]. One warp per dst node,
// thread t owns float4 cols [4t, 4t+3]. Depends only on F + CSR (not hp).
// ---------------------------------------------------------------------------
__global__ void agg_F_kernel(const float* __restrict__ F, const int* __restrict__ csr_src,
                             const int* __restrict__ rowptr, float* __restrict__ out) {
    int d = blockIdx.x;
    int col4 = threadIdx.x * 4;
    int s = rowptr[d], e = rowptr[d + 1];
    float4 a = make_float4(0.f, 0.f, 0.f, 0.f);
    int p = s;
    for (; p + 8 <= e; p += 8) {
#pragma unroll
        for (int j = 0; j < 8; j++) {
            int sr = __ldg(&csr_src[p + j]);
            float4 v = *(const float4*)(F + (size_t)sr * PD_IN + col4);
            a.x += v.x; a.y += v.y; a.z += v.z; a.w += v.w;
        }
    }
    for (; p < e; p++) {
        int sr = __ldg(&csr_src[p]);
        float4 v = *(const float4*)(F + (size_t)sr * PD_IN + col4);
        a.x += v.x; a.y += v.y; a.z += v.z; a.w += v.w;
    }
    int deg = e - s;
    float inv = (deg > 0) ? 1.0f / (float)deg : 0.0f;
    a.x *= inv; a.y *= inv; a.z *= inv; a.w *= inv;
    *(float4*)(out + (size_t)d * PD_CAT + col4) = a;
}

// ---------------------------------------------------------------------------
// Mean aggregation of hp columns into agg0[:, 128:192]. One warp per dst node,
// thread t owns float2 cols [2t, 2t+1]. Depends on hp + CSR.
// ---------------------------------------------------------------------------
__global__ void agg_HP_kernel(const float* __restrict__ HP, const int* __restrict__ csr_src,
                              const int* __restrict__ rowptr, float* __restrict__ out) {
    int d = blockIdx.x;
    int col2 = threadIdx.x * 2;
    int s = rowptr[d], e = rowptr[d + 1];
    float2 a = make_float2(0.f, 0.f);
    int p = s;
    for (; p + 8 <= e; p += 8) {
#pragma unroll
        for (int j = 0; j < 8; j++) {
            int sr = __ldg(&csr_src[p + j]);
            float2 v = *(const float2*)(HP + (size_t)sr * PD_PROMPT + col2);
            a.x += v.x; a.y += v.y;
        }
    }
    for (; p < e; p++) {
        int sr = __ldg(&csr_src[p]);
        float2 v = *(const float2*)(HP + (size_t)sr * PD_PROMPT + col2);
        a.x += v.x; a.y += v.y;
    }
    int deg = e - s;
    float inv = (deg > 0) ? 1.0f / (float)deg : 0.0f;
    a.x *= inv; a.y *= inv;
    *(float2*)(out + (size_t)d * PD_CAT + PD_IN + col2) = a;
}

// ---------------------------------------------------------------------------
// Mean aggregation, contiguous rows, float4: C/4 threads per dst node.
// ---------------------------------------------------------------------------
__global__ void agg_kernel(const float* __restrict__ H, const int* __restrict__ csr_src,
                           const int* __restrict__ rowptr, float* __restrict__ out, int C) {
    int d = blockIdx.x;
    int col4 = threadIdx.x * 4;
    int s = rowptr[d], e = rowptr[d + 1];
    float4 a = make_float4(0.f, 0.f, 0.f, 0.f);
    int p = s;
    for (; p + 8 <= e; p += 8) {
#pragma unroll
        for (int j = 0; j < 8; j++) {
            int sr = __ldg(&csr_src[p + j]);
            float4 v = *(const float4*)(H + (size_t)sr * C + col4);
            a.x += v.x; a.y += v.y; a.z += v.z; a.w += v.w;
        }
    }
    for (; p < e; p++) {
        int sr = __ldg(&csr_src[p]);
        float4 v = *(const float4*)(H + (size_t)sr * C + col4);
        a.x += v.x; a.y += v.y; a.z += v.z; a.w += v.w;
    }
    int deg = e - s;
    float inv = (deg > 0) ? 1.0f / (float)deg : 0.0f;
    a.x *= inv; a.y *= inv; a.z *= inv; a.w *= inv;
    *(float4*)(out + (size_t)d * C + col4) = a;
}

// ---------------------------------------------------------------------------
// Classifier: warp per row, D_HID=256 -> 2 outputs
// ---------------------------------------------------------------------------
__global__ void cls_kernel(const float* __restrict__ H2, const float* __restrict__ Wc,
                           const float* __restrict__ bc, float* __restrict__ out, int n) {
    int gwarp = (blockIdx.x * blockDim.x + threadIdx.x) >> 5;
    int lane = threadIdx.x & 31;
    if (gwarp >= n) return;
    const float* row = H2 + (size_t)gwarp * PD_HID;
    float c0 = 0.f, c1 = 0.f;
#pragma unroll
    for (int k = lane; k < PD_HID; k += 32) {
        float v = row[k];
        c0 += v * Wc[k * 2 + 0];
        c1 += v * Wc[k * 2 + 1];
    }
#pragma unroll
    for (int off = 16; off; off >>= 1) {
        c0 += __shfl_down_sync(0xFFFFFFFFu, c0, off);
        c1 += __shfl_down_sync(0xFFFFFFFFu, c1, off);
    }
    if (lane == 0) {
        out[gwarp * 2 + 0] = c0 + bc[0];
        out[gwarp * 2 + 1] = c1 + bc[1];
    }
}

// ---------------------------------------------------------------------------
// Launch
// ---------------------------------------------------------------------------
static void* symaddr(const void* sym) {
    void* p = nullptr;
    cudaGetSymbolAddress(&p, sym);
    return p;
}

extern "C" void kernel_launch(void* const* d_in, const int* in_sizes, int n_in,
                              void* d_out, int out_size) {
    const float* features = (const float*)d_in[0];
    const int* mask       = (const int*)d_in[1];
    const int* src0       = (const int*)d_in[2];
    const int* dst0       = (const int*)d_in[3];
    const int* src1       = (const int*)d_in[4];
    const int* dst1       = (const int*)d_in[5];
    // d_in[6] = output_nodes_indices (unused by reference)
    const float* w_pin    = (const float*)d_in[7];
    const float* b_pin    = (const float*)d_in[8];
    const float* w_pout   = (const float*)d_in[9];
    const float* b_pout   = (const float*)d_in[10];
    const float* w_self0  = (const float*)d_in[11];
    const float* w_neigh0 = (const float*)d_in[12];
    const float* b0       = (const float*)d_in[13];
    const float* w_self1  = (const float*)d_in[14];
    const float* w_neigh1 = (const float*)d_in[15];
    const float* b1       = (const float*)d_in[16];
    const float* w_cls    = (const float*)d_in[17];
    const float* b_cls    = (const float*)d_in[18];
    float* out = (float*)d_out;

    float* hp   = (float*)symaddr(g_hp);
    float* agg0 = (float*)symaddr(g_agg0);
    float* h1   = (float*)symaddr(g_h1);
    float* agg1 = (float*)symaddr(g_agg1);
    float* h2   = (float*)symaddr(g_h2);
    int* cnt0    = (int*)symaddr(g_cnt0);
    int* fill0   = (int*)symaddr(g_fill0);
    int* rowptr0 = (int*)symaddr(g_rowptr0);
    int* cnt1    = (int*)symaddr(g_cnt1);
    int* fill1   = (int*)symaddr(g_fill1);
    int* rowptr1 = (int*)symaddr(g_rowptr1);
    int* csr0    = (int*)symaddr(g_csr0);
    int* csr1    = (int*)symaddr(g_csr1);

    cudaStream_t s0 = 0;          // captured main stream
    cudaStream_t s1 = g_res.s1;   // side stream (CSR, self-GEMMs)
    cudaStream_t s2 = g_res.s2;   // side stream (agg_F)

    // Fork: CSR build chain on s1, prompt GEMM on s0.
    cudaEventRecord(g_res.ev_start, s0);
    cudaStreamWaitEvent(s1, g_res.ev_start, 0);
    cudaStreamWaitEvent(s2, g_res.ev_start, 0);

    zero4_kernel<<<(PN1 + 255) / 256, 256, 0, s1>>>(cnt0, PN1, fill0, PN1, cnt1, PN2, fill1, PN2);
    hist2_kernel<<<(PE0 + 255) / 256, 256, 0, s1>>>(dst0, PE0, cnt0, dst1, PE1, cnt1);
    scan2_kernel<<<2, 1024, 0, s1>>>(cnt0, rowptr0, PN1, cnt1, rowptr1, PN2);
    scatter2_kernel<<<(PE0 + 255) / 256, 256, 0, s1>>>(src0, dst0, PE0, rowptr0, fill0, csr0,
                                                       src1, dst1, PE1, rowptr1, fill1, csr1);
    cudaEventRecord(g_res.ev_csr, s1);

    // s0: hp = relu(select(F @ [w_pin|w_pout]) + bias)
    {
        dim3 grid(1, (PN0 + TBM - 1) / TBM);
        prompt_gemm_tf32_kernel<<<grid, 256, 0, s0>>>(features, w_pin, w_pout, mask,
                                                      b_pin, b_pout, hp, PN0);
    }
    cudaEventRecord(g_res.ev_hp, s0);

    // s2: F-part aggregation (needs only CSR + F) — overlaps prompt GEMM.
    cudaStreamWaitEvent(s2, g_res.ev_csr, 0);
    agg_F_kernel<<<PN1, 32, 0, s2>>>(features, csr0, rowptr0, agg0);
    cudaEventRecord(g_res.ev_aggF, s2);

    // s1: self-GEMM layer 0 (needs hp): h1 = [F|hp]@w_self0 + b0
    cudaStreamWaitEvent(s1, g_res.ev_hp, 0);
    {
        dim3 grid(PD_HID / TBN, (PN1 + TBM - 1) / TBM);
        gemm3_tf32_kernel<<<grid, 256, 0, s1>>>(
            features, w_self0, PD_IN,
            hp, w_self0 + (size_t)PD_IN * PD_HID, PD_PROMPT,
            nullptr, nullptr, 0,
            b0, h1, PN1, PD_HID, /*flags=*/0);
    }
    cudaEventRecord(g_res.ev_self0, s1);

    // s0: hp-part aggregation (needs CSR + hp)
    cudaStreamWaitEvent(s0, g_res.ev_csr, 0);
    agg_HP_kernel<<<PN1, 32, 0, s0>>>(hp, csr0, rowptr0, agg0);

    // s0: neigh-GEMM layer 0: h1 = relu(agg0@w_neigh0 + h1)
    cudaStreamWaitEvent(s0, g_res.ev_aggF, 0);
    cudaStreamWaitEvent(s0, g_res.ev_self0, 0);
    {
        dim3 grid(PD_HID / TBN, (PN1 + TBM - 1) / TBM);
        gemm3_tf32_kernel<<<grid, 256, 0, s0>>>(
            agg0, w_neigh0, PD_CAT,
            nullptr, nullptr, 0, nullptr, nullptr, 0,
            nullptr, h1, PN1, PD_HID, /*flags=*/3);  // addC + relu
    }
    cudaEventRecord(g_res.ev_h1, s0);

    // s1: self-GEMM layer 1: h2 = h1@w_self1 + b1
    cudaStreamWaitEvent(s1, g_res.ev_h1, 0);
    {
        dim3 grid(PD_HID / TBN, (PN2 + TBM - 1) / TBM);
        gemm3_tf32_kernel<<<grid, 256, 0, s1>>>(
            h1, w_self1, PD_HID,
            nullptr, nullptr, 0, nullptr, nullptr, 0,
            b1, h2, PN2, PD_HID, /*flags=*/0);
    }
    cudaEventRecord(g_res.ev_self1, s1);

    // s0: aggregation layer 1 (needs h1 + CSR)
    agg_kernel<<<PN2, PD_HID / 4, 0, s0>>>(h1, csr1, rowptr1, agg1, PD_HID);

    // s0: neigh-GEMM layer 1: h2 = agg1@w_neigh1 + h2 (no relu)
    cudaStreamWaitEvent(s0, g_res.ev_self1, 0);
    {
        dim3 grid(PD_HID / TBN, (PN2 + TBM - 1) / TBM);
        gemm3_tf32_kernel<<<grid, 256, 0, s0>>>(
            agg1, w_neigh1, PD_HID,
            nullptr, nullptr, 0, nullptr, nullptr, 0,
            nullptr, h2, PN2, PD_HID, /*flags=*/2);  // addC
    }

    // Classifier
    cls_kernel<<<(PN2 * 32 + 255) / 256, 256, 0, s0>>>(h2, w_cls, b_cls, out, PN2);
}

// round 11
// speedup vs baseline: 1.2294x; 1.2294x over previous
#include <cuda_runtime.h>
#include <cstdint>

// Problem dimensions (fixed by the reference)
#define PN0 200000
#define PN1 50000
#define PN2 10000
#define PD_IN 128
#define PD_PROMPT 64
#define PD_CAT 192
#define PD_HID 256
#define PE0 800000
#define PE1 160000

// ---------------------------------------------------------------------------
// Scratch (device globals; no allocations allowed)
// ---------------------------------------------------------------------------
__device__ float g_hp[(size_t)PN0 * PD_PROMPT];  // selected prompt (relu'd, tf32-rounded)
__device__ float g_agg0[(size_t)PN1 * PD_CAT];   // mean-agg of [F|hp] (tf32-rounded)
__device__ float g_h1[(size_t)PN1 * PD_HID];     // tf32-rounded
__device__ float g_agg1[(size_t)PN2 * PD_HID];   // tf32-rounded
__device__ float g_h2[(size_t)PN2 * PD_HID];
__device__ int g_cnt0[PN1], g_fill0[PN1], g_rowptr0[PN1 + 1];
__device__ int g_cnt1[PN2], g_fill1[PN2], g_rowptr1[PN2 + 1];
__device__ int g_csr0[PE0], g_csr1[PE1];
// tf32-pre-rounded weights
__device__ float g_wp[128 * 128];       // [w_pin | w_pout] packed along N
__device__ float g_ws0[384 * 256];      // w_self0 rounded
__device__ float g_wn0[192 * 256];      // w_neigh0 rounded
__device__ float g_ws1[256 * 256];      // w_self1 rounded
__device__ float g_wn1[256 * 256];      // w_neigh1 rounded

// ---------------------------------------------------------------------------
// Streams/events for graph-capturable fork/join (static-init, reused).
// ---------------------------------------------------------------------------
struct ExecRes {
    cudaStream_t s1, s2;
    cudaEvent_t ev_start, ev_csr, ev_hp, ev_aggF, ev_self0, ev_h1, ev_self1;
    ExecRes() {
        cudaStreamCreateWithFlags(&s1, cudaStreamNonBlocking);
        cudaStreamCreateWithFlags(&s2, cudaStreamNonBlocking);
        cudaEventCreateWithFlags(&ev_start, cudaEventDisableTiming);
        cudaEventCreateWithFlags(&ev_csr, cudaEventDisableTiming);
        cudaEventCreateWithFlags(&ev_hp, cudaEventDisableTiming);
        cudaEventCreateWithFlags(&ev_aggF, cudaEventDisableTiming);
        cudaEventCreateWithFlags(&ev_self0, cudaEventDisableTiming);
        cudaEventCreateWithFlags(&ev_h1, cudaEventDisableTiming);
        cudaEventCreateWithFlags(&ev_self1, cudaEventDisableTiming);
    }
};
static ExecRes g_res;

// ---------------------------------------------------------------------------
// tf32 + async-copy helpers
// ---------------------------------------------------------------------------
__device__ __forceinline__ uint32_t f2tf(float f) {
    uint32_t u;
    asm("cvt.rna.tf32.f32 %0, %1;" : "=r"(u) : "f"(f));
    return u;
}
__device__ __forceinline__ float rnd_tf32(float f) { return __uint_as_float(f2tf(f)); }

__device__ __forceinline__ void mma_tf32(float& c0, float& c1, float& c2, float& c3,
                                         uint32_t a0, uint32_t a1, uint32_t a2, uint32_t a3,
                                         uint32_t b0, uint32_t b1) {
    asm volatile(
        "mma.sync.aligned.m16n8k8.row.col.f32.tf32.tf32.f32 "
        "{%0,%1,%2,%3}, {%4,%5,%6,%7}, {%8,%9}, {%0,%1,%2,%3};"
        : "+f"(c0), "+f"(c1), "+f"(c2), "+f"(c3)
        : "r"(a0), "r"(a1), "r"(a2), "r"(a3), "r"(b0), "r"(b1));
}

__device__ __forceinline__ void cp16(uint32_t saddr, const void* gptr, int src_bytes) {
    asm volatile("cp.async.cg.shared.global [%0], [%1], 16, %2;"
                 :: "r"(saddr), "l"(gptr), "r"(src_bytes));
}
#define CP_COMMIT() asm volatile("cp.async.commit_group;" ::: "memory")
#define CP_WAIT1() asm volatile("cp.async.wait_group 1;" ::: "memory")
#define CP_WAIT0() asm volatile("cp.async.wait_group 0;" ::: "memory")

// ---------------------------------------------------------------------------
// Weight pre-rounding + packing (runs once per launch, ~1.2 MB)
// ---------------------------------------------------------------------------
__global__ void round_weights_kernel(const float* __restrict__ w_pin, const float* __restrict__ w_pout,
                                     const float* __restrict__ w_self0, const float* __restrict__ w_neigh0,
                                     const float* __restrict__ w_self1, const float* __restrict__ w_neigh1,
                                     float* __restrict__ wp, float* __restrict__ ws0,
                                     float* __restrict__ wn0, float* __restrict__ ws1,
                                     float* __restrict__ wn1) {
    int i = blockIdx.x * blockDim.x + threadIdx.x;
    if (i < 128 * 128) {
        int k = i >> 7, j = i & 127;
        float v = (j < 64) ? w_pin[k * 64 + j] : w_pout[k * 64 + (j - 64)];
        wp[i] = rnd_tf32(v);
    }
    if (i < 384 * 256) ws0[i] = rnd_tf32(w_self0[i]);
    if (i < 192 * 256) wn0[i] = rnd_tf32(w_neigh0[i]);
    if (i < 256 * 256) { ws1[i] = rnd_tf32(w_self1[i]); wn1[i] = rnd_tf32(w_neigh1[i]); }
}

// ---------------------------------------------------------------------------
// CSR build kernels
// ---------------------------------------------------------------------------
__global__ void zero4_kernel(int* a, int na, int* b, int nb, int* c, int nc, int* d, int nd) {
    int i = blockIdx.x * blockDim.x + threadIdx.x;
    if (i < na) a[i] = 0;
    if (i < nb) b[i] = 0;
    if (i < nc) c[i] = 0;
    if (i < nd) d[i] = 0;
}

__global__ void hist2_kernel(const int* __restrict__ dst0, int E0, int* __restrict__ cnt0,
                             const int* __restrict__ dst1, int E1, int* __restrict__ cnt1) {
    int i = blockIdx.x * blockDim.x + threadIdx.x;
    if (i < E0) atomicAdd(&cnt0[dst0[i]], 1);
    if (i < E1) atomicAdd(&cnt1[dst1[i]], 1);
}

__device__ void scan_body(const int* __restrict__ cnt, int* __restrict__ rowptr, int n) {
    __shared__ int warp_sums[32];
    __shared__ int s_carry;
    const int tid = threadIdx.x;
    const int lane = tid & 31;
    const int warp = tid >> 5;
    if (tid == 0) { s_carry = 0; rowptr[0] = 0; }
    __syncthreads();

    const int TILE = 4096;
    for (int base = 0; base < n; base += TILE) {
        int i0 = base + tid * 4;
        int4 v = make_int4(0, 0, 0, 0);
        if (i0 + 3 < n) {
            v = *(const int4*)(cnt + i0);
        } else {
            if (i0 + 0 < n) v.x = cnt[i0 + 0];
            if (i0 + 1 < n) v.y = cnt[i0 + 1];
            if (i0 + 2 < n) v.z = cnt[i0 + 2];
        }
        int s1 = v.x, s2 = s1 + v.y, s3 = s2 + v.z, s4 = s3 + v.w;
        int t = s4;
#pragma unroll
        for (int off = 1; off < 32; off <<= 1) {
            int u = __shfl_up_sync(0xFFFFFFFFu, t, off);
            if (lane >= off) t += u;
        }
        if (lane == 31) warp_sums[warp] = t;
        __syncthreads();
        if (warp == 0) {
            int w = warp_sums[lane];
            int tw = w;
#pragma unroll
            for (int off = 1; off < 32; off <<= 1) {
                int u = __shfl_up_sync(0xFFFFFFFFu, tw, off);
                if (lane >= off) tw += u;
            }
            warp_sums[lane] = tw - w;
        }
        __syncthreads();
        int excl = s_carry + warp_sums[warp] + (t - s4);
        if (i0 + 0 < n) rowptr[i0 + 1] = excl + s1;
        if (i0 + 1 < n) rowptr[i0 + 2] = excl + s2;
        if (i0 + 2 < n) rowptr[i0 + 3] = excl + s3;
        if (i0 + 3 < n) rowptr[i0 + 4] = excl + s4;
        __syncthreads();
        if (tid == 1023) s_carry = excl + s4;
    }
}

__global__ void scan2_kernel(const int* c0, int* r0, int n0,
                             const int* c1, int* r1, int n1) {
    if (blockIdx.x == 0) scan_body(c0, r0, n0);
    else scan_body(c1, r1, n1);
}

__global__ void scatter2_kernel(const int* __restrict__ src0, const int* __restrict__ dst0, int E0,
                                const int* __restrict__ rowptr0, int* __restrict__ fill0,
                                int* __restrict__ csr0,
                                const int* __restrict__ src1, const int* __restrict__ dst1, int E1,
                                const int* __restrict__ rowptr1, int* __restrict__ fill1,
                                int* __restrict__ csr1) {
    int i = blockIdx.x * blockDim.x + threadIdx.x;
    if (i < E0) {
        int d = dst0[i];
        int pos = rowptr0[d] + atomicAdd(&fill0[d], 1);
        csr0[pos] = src0[i];
    }
    if (i < E1) {
        int d = dst1[i];
        int pos = rowptr1[d] + atomicAdd(&fill1[d], 1);
        csr1[pos] = src1[i];
    }
}

// ---------------------------------------------------------------------------
// tf32 tensor-core GEMM, cp.async 2-stage pipeline.
// BM=128, BN=128, BK=32, 256 threads (8 warps 2x4), warp tile 64x32.
// Stage layout (dynamic smem, words): A[m*36+k] (128x32 pad36), then
// B[k*136+n] (32x128 pad136). 2 stages = 71680 bytes.
// Inputs are pre-rounded to tf32 by producers (except F: truncation, accepted).
// ---------------------------------------------------------------------------
#define TBM 128
#define TBN 128
#define TBK 32
#define AS_STRIDE 36
#define BS_STRIDE 136
#define STAGE_A (TBM * AS_STRIDE)          // 4608 words
#define STAGE_B (TBK * BS_STRIDE)          // 4352 words
#define STAGE_W (STAGE_A + STAGE_B)        // 8960 words
#define GEMM_SMEM_BYTES (2 * STAGE_W * 4)  // 71680 bytes

#define SEG_RESOLVE(kt, Aout, Bout, kload, lda)                                 \
    if ((kt) < K1) { Aout = A1; Bout = B1; kload = (kt); lda = K1; }            \
    else if ((kt) < K1 + K2) { Aout = A2; Bout = B2; kload = (kt) - K1; lda = K2; } \
    else { Aout = A3; Bout = B3; kload = (kt) - K1 - K2; lda = K3; }

// Issue cp.asyncs for one k-tile into stage `st`.
#define ASYNC_LOAD(st, kt)                                                      \
    {                                                                           \
        const float *A_, *B_; int kload_, lda_;                                 \
        SEG_RESOLVE(kt, A_, B_, kload_, lda_);                                  \
        uint32_t abase = smem_u32 + (st) * (STAGE_W * 4);                       \
        uint32_t bbase = abase + STAGE_A * 4;                                   \
        _Pragma("unroll")                                                       \
        for (int i = 0; i < 4; i++) {                                           \
            int idx = tid + i * 256;                                            \
            int m = idx >> 3, kq = (idx & 7) * 4;                               \
            int grow = block_row + m;                                           \
            cp16(abase + (m * AS_STRIDE + kq) * 4,                              \
                 A_ + (size_t)grow * lda_ + kload_ + kq, grow < M ? 16 : 0);    \
        }                                                                       \
        _Pragma("unroll")                                                       \
        for (int i = 0; i < 4; i++) {                                           \
            int idx = tid + i * 256;                                            \
            int k = idx >> 5, n4 = (idx & 31) * 4;                              \
            cp16(bbase + (k * BS_STRIDE + n4) * 4,                              \
                 B_ + (size_t)(kload_ + k) * N + block_col + n4, 16);           \
        }                                                                       \
    }

#define T_COMPUTE(Asb, Bsb)                                                     \
    {                                                                           \
        _Pragma("unroll")                                                       \
        for (int ks = 0; ks < 4; ks++) {                                        \
            uint32_t af[4][4], bf[4][2];                                        \
            _Pragma("unroll")                                                   \
            for (int mt = 0; mt < 4; mt++) {                                    \
                int mb = warpM + 16 * mt + qr;                                  \
                int kb = 8 * ks + qc;                                           \
                af[mt][0] = (Asb)[mb * AS_STRIDE + kb];                         \
                af[mt][1] = (Asb)[(mb + 8) * AS_STRIDE + kb];                   \
                af[mt][2] = (Asb)[mb * AS_STRIDE + kb + 4];                     \
                af[mt][3] = (Asb)[(mb + 8) * AS_STRIDE + kb + 4];               \
            }                                                                   \
            _Pragma("unroll")                                                   \
            for (int nt = 0; nt < 4; nt++) {                                    \
                int nb = warpN + 8 * nt + qr;                                   \
                int kb = 8 * ks + qc;                                           \
                bf[nt][0] = (Bsb)[kb * BS_STRIDE + nb];                         \
                bf[nt][1] = (Bsb)[(kb + 4) * BS_STRIDE + nb];                   \
            }                                                                   \
            _Pragma("unroll")                                                   \
            for (int mt = 0; mt < 4; mt++)                                      \
                _Pragma("unroll")                                               \
                for (int nt = 0; nt < 4; nt++)                                  \
                    mma_tf32(acc[mt][nt][0], acc[mt][nt][1],                    \
                             acc[mt][nt][2], acc[mt][nt][3],                    \
                             af[mt][0], af[mt][1], af[mt][2], af[mt][3],        \
                             bf[nt][0], bf[nt][1]);                             \
        }                                                                       \
    }

#define T_PROLOG()                                                              \
    extern __shared__ uint32_t dynsmem[];                                       \
    const uint32_t smem_u32 = (uint32_t)__cvta_generic_to_shared(dynsmem);      \
    const int tid = threadIdx.x;                                                \
    const int wid = tid >> 5;                                                   \
    const int lane = tid & 31;                                                  \
    const int qr = lane >> 2;                                                   \
    const int qc = lane & 3;                                                    \
    const int warpM = (wid & 1) * 64;                                           \
    const int warpN = (wid >> 1) * 32;                                          \
    float acc[4][4][4];                                                         \
    _Pragma("unroll")                                                           \
    for (int a = 0; a < 4; a++)                                                 \
        _Pragma("unroll")                                                       \
        for (int b = 0; b < 4; b++)                                             \
            _Pragma("unroll")                                                   \
            for (int c = 0; c < 4; c++) acc[a][b][c] = 0.0f;

#define T_MAINLOOP(Ktot)                                                        \
    {                                                                           \
        const int ntile = (Ktot) / TBK;                                         \
        ASYNC_LOAD(0, 0);                                                       \
        CP_COMMIT();                                                            \
        for (int t = 0; t < ntile; t++) {                                       \
            int stage = t & 1;                                                  \
            if (t + 1 < ntile) {                                                \
                ASYNC_LOAD((t + 1) & 1, (t + 1) * TBK);                         \
                CP_COMMIT();                                                    \
                CP_WAIT1();                                                     \
            } else {                                                            \
                CP_WAIT0();                                                     \
            }                                                                   \
            __syncthreads();                                                    \
            uint32_t* Asb = dynsmem + stage * STAGE_W;                          \
            uint32_t* Bsb = Asb + STAGE_A;                                      \
            T_COMPUTE(Asb, Bsb);                                                \
            __syncthreads();                                                    \
        }                                                                       \
    }

// Triple-K-segment GEMM: C = [A1|A2|A3] @ [B1;B2;B3] (+bias) (+C) (relu).
// flags: bit0 = relu, bit1 = addC, bit2 = round output to tf32.
__global__ __launch_bounds__(256, 2)
void gemm3_tf32_kernel(const float* __restrict__ A1, const float* __restrict__ B1, int K1,
                       const float* __restrict__ A2, const float* __restrict__ B2, int K2,
                       const float* __restrict__ A3, const float* __restrict__ B3, int K3,
                       const float* __restrict__ bias, float* __restrict__ C,
                       int M, int N, int flags) {
    const int block_row = blockIdx.y * TBM;
    const int block_col = blockIdx.x * TBN;
    T_PROLOG();
    T_MAINLOOP(K1 + K2 + K3);

    const bool doRelu = (flags & 1) != 0;
    const bool doAdd = (flags & 2) != 0;
    const bool doRound = (flags & 4) != 0;
#pragma unroll
    for (int mt = 0; mt < 4; mt++) {
        int r0 = block_row + warpM + 16 * mt + qr;
        int r1 = r0 + 8;
#pragma unroll
        for (int nt = 0; nt < 4; nt++) {
            int col = block_col + warpN + 8 * nt + 2 * qc;
            float bx = 0.f, by = 0.f;
            if (bias) { bx = bias[col]; by = bias[col + 1]; }
            float v0 = acc[mt][nt][0] + bx, v1 = acc[mt][nt][1] + by;
            float v2 = acc[mt][nt][2] + bx, v3 = acc[mt][nt][3] + by;
            if (r0 < M) {
                if (doAdd) {
                    float2 c = *(const float2*)(C + (size_t)r0 * N + col);
                    v0 += c.x; v1 += c.y;
                }
                if (doRelu) { v0 = fmaxf(v0, 0.f); v1 = fmaxf(v1, 0.f); }
                if (doRound) { v0 = rnd_tf32(v0); v1 = rnd_tf32(v1); }
                *(float2*)(C + (size_t)r0 * N + col) = make_float2(v0, v1);
            }
            if (r1 < M) {
                if (doAdd) {
                    float2 c = *(const float2*)(C + (size_t)r1 * N + col);
                    v2 += c.x; v3 += c.y;
                }
                if (doRelu) { v2 = fmaxf(v2, 0.f); v3 = fmaxf(v3, 0.f); }
                if (doRound) { v2 = rnd_tf32(v2); v3 = rnd_tf32(v3); }
                *(float2*)(C + (size_t)r1 * N + col) = make_float2(v2, v3);
            }
        }
    }
}

// Prompt GEMM: P = F @ g_wp (N=128, pre-rounded packed weights).
// Epilogue: per-row mask select, +bias, relu, tf32-round, write hp[N0 x 64].
__global__ __launch_bounds__(256, 2)
void prompt_gemm_tf32_kernel(const float* __restrict__ A1, const float* __restrict__ B1,
                             const int* __restrict__ mask,
                             const float* __restrict__ b_pin, const float* __restrict__ b_pout,
                             float* __restrict__ hp, int M) {
    const int block_row = blockIdx.y * TBM;
    const int block_col = 0;
    const int N = 128;
    const int K1 = PD_IN, K2 = 0, K3 = 0;
    const float* A2 = nullptr; const float* B2 = nullptr;
    const float* A3 = nullptr; const float* B3 = nullptr;
    T_PROLOG();
    T_MAINLOOP(PD_IN);

#pragma unroll
    for (int mt = 0; mt < 4; mt++) {
        int r0 = block_row + warpM + 16 * mt + qr;
        int r1 = r0 + 8;
        bool m0 = (r0 < M) && (mask[r0 < M ? r0 : 0] != 0);
        bool m1 = (r1 < M) && (mask[r1 < M ? r1 : 0] != 0);
#pragma unroll
        for (int nt = 0; nt < 4; nt++) {
            int col = warpN + 8 * nt + 2 * qc;  // 0..126, pair within one half
            bool isIn = col < 64;
            int dcol = isIn ? col : col - 64;
            float bx = isIn ? b_pin[dcol] : b_pout[dcol];
            float by = isIn ? b_pin[dcol + 1] : b_pout[dcol + 1];
            if (r0 < M && (isIn == m0)) {
                float2 o = make_float2(rnd_tf32(fmaxf(acc[mt][nt][0] + bx, 0.f)),
                                       rnd_tf32(fmaxf(acc[mt][nt][1] + by, 0.f)));
                *(float2*)(hp + (size_t)r0 * PD_PROMPT + dcol) = o;
            }
            if (r1 < M && (isIn == m1)) {
                float2 o = make_float2(rnd_tf32(fmaxf(acc[mt][nt][2] + bx, 0.f)),
                                       rnd_tf32(fmaxf(acc[mt][nt][3] + by, 0.f)));
                *(float2*)(hp + (size_t)r1 * PD_PROMPT + dcol) = o;
            }
        }
    }
}

// ---------------------------------------------------------------------------
// Mean aggregation of F columns into agg0[:, 0:128] (tf32-rounded output).
// One warp per dst node, thread t owns float4 cols [4t, 4t+3].
// ---------------------------------------------------------------------------
__global__ void agg_F_kernel(const float* __restrict__ F, const int* __restrict__ csr_src,
                             const int* __restrict__ rowptr, float* __restrict__ out) {
    int d = blockIdx.x;
    int col4 = threadIdx.x * 4;
    int s = rowptr[d], e = rowptr[d + 1];
    float4 a = make_float4(0.f, 0.f, 0.f, 0.f);
    int p = s;
    for (; p + 8 <= e; p += 8) {
#pragma unroll
        for (int j = 0; j < 8; j++) {
            int sr = __ldg(&csr_src[p + j]);
            float4 v = *(const float4*)(F + (size_t)sr * PD_IN + col4);
            a.x += v.x; a.y += v.y; a.z += v.z; a.w += v.w;
        }
    }
    for (; p < e; p++) {
        int sr = __ldg(&csr_src[p]);
        float4 v = *(const float4*)(F + (size_t)sr * PD_IN + col4);
        a.x += v.x; a.y += v.y; a.z += v.z; a.w += v.w;
    }
    int deg = e - s;
    float inv = (deg > 0) ? 1.0f / (float)deg : 0.0f;
    a.x = rnd_tf32(a.x * inv); a.y = rnd_tf32(a.y * inv);
    a.z = rnd_tf32(a.z * inv); a.w = rnd_tf32(a.w * inv);
    *(float4*)(out + (size_t)d * PD_CAT + col4) = a;
}

// ---------------------------------------------------------------------------
// Mean aggregation of hp columns into agg0[:, 128:192] (tf32-rounded output).
// ---------------------------------------------------------------------------
__global__ void agg_HP_kernel(const float* __restrict__ HP, const int* __restrict__ csr_src,
                              const int* __restrict__ rowptr, float* __restrict__ out) {
    int d = blockIdx.x;
    int col2 = threadIdx.x * 2;
    int s = rowptr[d], e = rowptr[d + 1];
    float2 a = make_float2(0.f, 0.f);
    int p = s;
    for (; p + 8 <= e; p += 8) {
#pragma unroll
        for (int j = 0; j < 8; j++) {
            int sr = __ldg(&csr_src[p + j]);
            float2 v = *(const float2*)(HP + (size_t)sr * PD_PROMPT + col2);
            a.x += v.x; a.y += v.y;
        }
    }
    for (; p < e; p++) {
        int sr = __ldg(&csr_src[p]);
        float2 v = *(const float2*)(HP + (size_t)sr * PD_PROMPT + col2);
        a.x += v.x; a.y += v.y;
    }
    int deg = e - s;
    float inv = (deg > 0) ? 1.0f / (float)deg : 0.0f;
    a.x = rnd_tf32(a.x * inv); a.y = rnd_tf32(a.y * inv);
    *(float2*)(out + (size_t)d * PD_CAT + PD_IN + col2) = a;
}

// ---------------------------------------------------------------------------
// Mean aggregation, contiguous rows, float4, tf32-rounded output.
// ---------------------------------------------------------------------------
__global__ void agg_kernel(const float* __restrict__ H, const int* __restrict__ csr_src,
                           const int* __restrict__ rowptr, float* __restrict__ out, int C) {
    int d = blockIdx.x;
    int col4 = threadIdx.x * 4;
    int s = rowptr[d], e = rowptr[d + 1];
    float4 a = make_float4(0.f, 0.f, 0.f, 0.f);
    int p = s;
    for (; p + 8 <= e; p += 8) {
#pragma unroll
        for (int j = 0; j < 8; j++) {
            int sr = __ldg(&csr_src[p + j]);
            float4 v = *(const float4*)(H + (size_t)sr * C + col4);
            a.x += v.x; a.y += v.y; a.z += v.z; a.w += v.w;
        }
    }
    for (; p < e; p++) {
        int sr = __ldg(&csr_src[p]);
        float4 v = *(const float4*)(H + (size_t)sr * C + col4);
        a.x += v.x; a.y += v.y; a.z += v.z; a.w += v.w;
    }
    int deg = e - s;
    float inv = (deg > 0) ? 1.0f / (float)deg : 0.0f;
    a.x = rnd_tf32(a.x * inv); a.y = rnd_tf32(a.y * inv);
    a.z = rnd_tf32(a.z * inv); a.w = rnd_tf32(a.w * inv);
    *(float4*)(out + (size_t)d * C + col4) = a;
}

// ---------------------------------------------------------------------------
// Classifier: warp per row, D_HID=256 -> 2 outputs
// ---------------------------------------------------------------------------
__global__ void cls_kernel(const float* __restrict__ H2, const float* __restrict__ Wc,
                           const float* __restrict__ bc, float* __restrict__ out, int n) {
    int gwarp = (blockIdx.x * blockDim.x + threadIdx.x) >> 5;
    int lane = threadIdx.x & 31;
    if (gwarp >= n) return;
    const float* row = H2 + (size_t)gwarp * PD_HID;
    float c0 = 0.f, c1 = 0.f;
#pragma unroll
    for (int k = lane; k < PD_HID; k += 32) {
        float v = row[k];
        c0 += v * Wc[k * 2 + 0];
        c1 += v * Wc[k * 2 + 1];
    }
#pragma unroll
    for (int off = 16; off; off >>= 1) {
        c0 += __shfl_down_sync(0xFFFFFFFFu, c0, off);
        c1 += __shfl_down_sync(0xFFFFFFFFu, c1, off);
    }
    if (lane == 0) {
        out[gwarp * 2 + 0] = c0 + bc[0];
        out[gwarp * 2 + 1] = c1 + bc[1];
    }
}

// ---------------------------------------------------------------------------
// Launch
// ---------------------------------------------------------------------------
static void* symaddr(const void* sym) {
    void* p = nullptr;
    cudaGetSymbolAddress(&p, sym);
    return p;
}

extern "C" void kernel_launch(void* const* d_in, const int* in_sizes, int n_in,
                              void* d_out, int out_size) {
    const float* features = (const float*)d_in[0];
    const int* mask       = (const int*)d_in[1];
    const int* src0       = (const int*)d_in[2];
    const int* dst0       = (const int*)d_in[3];
    const int* src1       = (const int*)d_in[4];
    const int* dst1       = (const int*)d_in[5];
    // d_in[6] = output_nodes_indices (unused by reference)
    const float* w_pin    = (const float*)d_in[7];
    const float* b_pin    = (const float*)d_in[8];
    const float* w_pout   = (const float*)d_in[9];
    const float* b_pout   = (const float*)d_in[10];
    const float* w_self0  = (const float*)d_in[11];
    const float* w_neigh0 = (const float*)d_in[12];
    const float* b0       = (const float*)d_in[13];
    const float* w_self1  = (const float*)d_in[14];
    const float* w_neigh1 = (const float*)d_in[15];
    const float* b1       = (const float*)d_in[16];
    const float* w_cls    = (const float*)d_in[17];
    const float* b_cls    = (const float*)d_in[18];
    float* out = (float*)d_out;

    float* hp   = (float*)symaddr(g_hp);
    float* agg0 = (float*)symaddr(g_agg0);
    float* h1   = (float*)symaddr(g_h1);
    float* agg1 = (float*)symaddr(g_agg1);
    float* h2   = (float*)symaddr(g_h2);
    float* wp   = (float*)symaddr(g_wp);
    float* ws0  = (float*)symaddr(g_ws0);
    float* wn0  = (float*)symaddr(g_wn0);
    float* ws1  = (float*)symaddr(g_ws1);
    float* wn1  = (float*)symaddr(g_wn1);
    int* cnt0    = (int*)symaddr(g_cnt0);
    int* fill0   = (int*)symaddr(g_fill0);
    int* rowptr0 = (int*)symaddr(g_rowptr0);
    int* cnt1    = (int*)symaddr(g_cnt1);
    int* fill1   = (int*)symaddr(g_fill1);
    int* rowptr1 = (int*)symaddr(g_rowptr1);
    int* csr0    = (int*)symaddr(g_csr0);
    int* csr1    = (int*)symaddr(g_csr1);

    // Opt-in to 70KB dynamic smem for the GEMM kernels (host-side, idempotent).
    cudaFuncSetAttribute(gemm3_tf32_kernel,
                         cudaFuncAttributeMaxDynamicSharedMemorySize, GEMM_SMEM_BYTES);
    cudaFuncSetAttribute(prompt_gemm_tf32_kernel,
                         cudaFuncAttributeMaxDynamicSharedMemorySize, GEMM_SMEM_BYTES);

    cudaStream_t s0 = 0;          // captured main stream
    cudaStream_t s1 = g_res.s1;   // side stream (CSR, self-GEMMs)
    cudaStream_t s2 = g_res.s2;   // side stream (agg_F)

    cudaEventRecord(g_res.ev_start, s0);
    cudaStreamWaitEvent(s1, g_res.ev_start, 0);
    cudaStreamWaitEvent(s2, g_res.ev_start, 0);

    // s1: CSR build chain
    zero4_kernel<<<(PN1 + 255) / 256, 256, 0, s1>>>(cnt0, PN1, fill0, PN1, cnt1, PN2, fill1, PN2);
    hist2_kernel<<<(PE0 + 255) / 256, 256, 0, s1>>>(dst0, PE0, cnt0, dst1, PE1, cnt1);
    scan2_kernel<<<2, 1024, 0, s1>>>(cnt0, rowptr0, PN1, cnt1, rowptr1, PN2);
    scatter2_kernel<<<(PE0 + 255) / 256, 256, 0, s1>>>(src0, dst0, PE0, rowptr0, fill0, csr0,
                                                       src1, dst1, PE1, rowptr1, fill1, csr1);
    cudaEventRecord(g_res.ev_csr, s1);

    // s0: weight pre-round/pack, then prompt GEMM
    round_weights_kernel<<<(384 * 256 + 255) / 256, 256, 0, s0>>>(
        w_pin, w_pout, w_self0, w_neigh0, w_self1, w_neigh1, wp, ws0, wn0, ws1, wn1);
    {
        dim3 grid(1, (PN0 + TBM - 1) / TBM);
        prompt_gemm_tf32_kernel<<<grid, 256, GEMM_SMEM_BYTES, s0>>>(
            features, wp, mask, b_pin, b_pout, hp, PN0);
    }
    cudaEventRecord(g_res.ev_hp, s0);

    // s2: F-part aggregation (needs only CSR + F) — overlaps prompt GEMM.
    cudaStreamWaitEvent(s2, g_res.ev_csr, 0);
    agg_F_kernel<<<PN1, 32, 0, s2>>>(features, csr0, rowptr0, agg0);
    cudaEventRecord(g_res.ev_aggF, s2);

    // s1: self-GEMM layer 0: h1 = [F|hp]@ws0 + b0 (no round: added later)
    cudaStreamWaitEvent(s1, g_res.ev_hp, 0);
    {
        dim3 grid(PD_HID / TBN, (PN1 + TBM - 1) / TBM);
        gemm3_tf32_kernel<<<grid, 256, GEMM_SMEM_BYTES, s1>>>(
            features, ws0, PD_IN,
            hp, ws0 + (size_t)PD_IN * PD_HID, PD_PROMPT,
            nullptr, nullptr, 0,
            b0, h1, PN1, PD_HID, /*flags=*/0);
    }
    cudaEventRecord(g_res.ev_self0, s1);

    // s0: hp-part aggregation
    cudaStreamWaitEvent(s0, g_res.ev_csr, 0);
    agg_HP_kernel<<<PN1, 32, 0, s0>>>(hp, csr0, rowptr0, agg0);

    // s0: neigh-GEMM layer 0: h1 = round(relu(agg0@wn0 + h1))
    cudaStreamWaitEvent(s0, g_res.ev_aggF, 0);
    cudaStreamWaitEvent(s0, g_res.ev_self0, 0);
    {
        dim3 grid(PD_HID / TBN, (PN1 + TBM - 1) / TBM);
        gemm3_tf32_kernel<<<grid, 256, GEMM_SMEM_BYTES, s0>>>(
            agg0, wn0, PD_CAT,
            nullptr, nullptr, 0, nullptr, nullptr, 0,
            nullptr, h1, PN1, PD_HID, /*flags=*/7);  // addC + relu + round
    }
    cudaEventRecord(g_res.ev_h1, s0);

    // s1: self-GEMM layer 1: h2 = h1@ws1 + b1
    cudaStreamWaitEvent(s1, g_res.ev_h1, 0);
    {
        dim3 grid(PD_HID / TBN, (PN2 + TBM - 1) / TBM);
        gemm3_tf32_kernel<<<grid, 256, GEMM_SMEM_BYTES, s1>>>(
            h1, ws1, PD_HID,
            nullptr, nullptr, 0, nullptr, nullptr, 0,
            b1, h2, PN2, PD_HID, /*flags=*/0);
    }
    cudaEventRecord(g_res.ev_self1, s1);

    // s0: aggregation layer 1
    agg_kernel<<<PN2, PD_HID / 4, 0, s0>>>(h1, csr1, rowptr1, agg1, PD_HID);

    // s0: neigh-GEMM layer 1: h2 = agg1@wn1 + h2 (no relu, no round)
    cudaStreamWaitEvent(s0, g_res.ev_self1, 0);
    {
        dim3 grid(PD_HID / TBN, (PN2 + TBM - 1) / TBM);
        gemm3_tf32_kernel<<<grid, 256, GEMM_SMEM_BYTES, s0>>>(
            agg1, wn1, PD_HID,
            nullptr, nullptr, 0, nullptr, nullptr, 0,
            nullptr, h2, PN2, PD_HID, /*flags=*/2);  // addC
    }

    // Classifier
    cls_kernel<<<(PN2 * 32 + 255) / 256, 256, 0, s0>>>(h2, w_cls, b_cls, out, PN2);
}

// round 12
// speedup vs baseline: 1.2614x; 1.0260x over previous
#include <cuda_runtime.h>
#include <cstdint>

// Problem dimensions (fixed by the reference)
#define PN0 200000
#define PN1 50000
#define PN2 10000
#define PD_IN 128
#define PD_PROMPT 64
#define PD_CAT 192
#define PD_HID 256
#define PE0 800000
#define PE1 160000

#define GLIST_LEN (PN0 + 128)  // padded partition list (128-aligned out-base)

// ---------------------------------------------------------------------------
// Scratch (device globals; no allocations allowed)
// ---------------------------------------------------------------------------
__device__ float g_hp[(size_t)PN0 * PD_PROMPT];  // selected prompt (relu'd, tf32-rounded)
__device__ float g_agg0[(size_t)PN1 * PD_CAT];
__device__ float g_h1[(size_t)PN1 * PD_HID];
__device__ float g_agg1[(size_t)PN2 * PD_HID];
__device__ float g_h2[(size_t)PN2 * PD_HID];
__device__ int g_cnt0[PN1], g_fill0[PN1], g_rowptr0[PN1 + 1];
__device__ int g_cnt1[PN2], g_fill1[PN2], g_rowptr1[PN2 + 1];
__device__ int g_csr0[PE0], g_csr1[PE1];
// partition state
__device__ int g_glist[GLIST_LEN];
__device__ int g_pc[4];  // [0]=n_in, [1]=fill_in, [2]=fill_out
// tf32-pre-rounded weights
__device__ float g_wpi[128 * 64];   // w_pin rounded
__device__ float g_wpo[128 * 64];   // w_pout rounded
__device__ float g_ws0[384 * 256];
__device__ float g_wn0[192 * 256];
__device__ float g_ws1[256 * 256];
__device__ float g_wn1[256 * 256];

// ---------------------------------------------------------------------------
// Streams/events (static-init, reused; graph-capturable fork/join)
// ---------------------------------------------------------------------------
struct ExecRes {
    cudaStream_t s1, s2;
    cudaEvent_t ev_start, ev_csr, ev_hp, ev_aggF, ev_self0, ev_h1, ev_self1;
    ExecRes() {
        cudaStreamCreateWithFlags(&s1, cudaStreamNonBlocking);
        cudaStreamCreateWithFlags(&s2, cudaStreamNonBlocking);
        cudaEventCreateWithFlags(&ev_start, cudaEventDisableTiming);
        cudaEventCreateWithFlags(&ev_csr, cudaEventDisableTiming);
        cudaEventCreateWithFlags(&ev_hp, cudaEventDisableTiming);
        cudaEventCreateWithFlags(&ev_aggF, cudaEventDisableTiming);
        cudaEventCreateWithFlags(&ev_self0, cudaEventDisableTiming);
        cudaEventCreateWithFlags(&ev_h1, cudaEventDisableTiming);
        cudaEventCreateWithFlags(&ev_self1, cudaEventDisableTiming);
    }
};
static ExecRes g_res;

// ---------------------------------------------------------------------------
// tf32 + async-copy helpers
// ---------------------------------------------------------------------------
__device__ __forceinline__ uint32_t f2tf(float f) {
    uint32_t u;
    asm("cvt.rna.tf32.f32 %0, %1;" : "=r"(u) : "f"(f));
    return u;
}
__device__ __forceinline__ float rnd_tf32(float f) { return __uint_as_float(f2tf(f)); }

__device__ __forceinline__ void mma_tf32(float& c0, float& c1, float& c2, float& c3,
                                         uint32_t a0, uint32_t a1, uint32_t a2, uint32_t a3,
                                         uint32_t b0, uint32_t b1) {
    asm volatile(
        "mma.sync.aligned.m16n8k8.row.col.f32.tf32.tf32.f32 "
        "{%0,%1,%2,%3}, {%4,%5,%6,%7}, {%8,%9}, {%0,%1,%2,%3};"
        : "+f"(c0), "+f"(c1), "+f"(c2), "+f"(c3)
        : "r"(a0), "r"(a1), "r"(a2), "r"(a3), "r"(b0), "r"(b1));
}

__device__ __forceinline__ void cp16(uint32_t saddr, const void* gptr, int src_bytes) {
    asm volatile("cp.async.cg.shared.global [%0], [%1], 16, %2;"
                 :: "r"(saddr), "l"(gptr), "r"(src_bytes));
}
#define CP_COMMIT() asm volatile("cp.async.commit_group;" ::: "memory")
#define CP_WAIT_G1() asm volatile("cp.async.wait_group 1;" ::: "memory")

// ---------------------------------------------------------------------------
// Weight pre-rounding
// ---------------------------------------------------------------------------
__global__ void round_weights_kernel(const float* __restrict__ w_pin, const float* __restrict__ w_pout,
                                     const float* __restrict__ w_self0, const float* __restrict__ w_neigh0,
                                     const float* __restrict__ w_self1, const float* __restrict__ w_neigh1,
                                     float* __restrict__ wpi, float* __restrict__ wpo,
                                     float* __restrict__ ws0, float* __restrict__ wn0,
                                     float* __restrict__ ws1, float* __restrict__ wn1) {
    int i = blockIdx.x * blockDim.x + threadIdx.x;
    if (i < 128 * 64) { wpi[i] = rnd_tf32(w_pin[i]); wpo[i] = rnd_tf32(w_pout[i]); }
    if (i < 384 * 256) ws0[i] = rnd_tf32(w_self0[i]);
    if (i < 192 * 256) wn0[i] = rnd_tf32(w_neigh0[i]);
    if (i < 256 * 256) { ws1[i] = rnd_tf32(w_self1[i]); wn1[i] = rnd_tf32(w_neigh1[i]); }
}

// ---------------------------------------------------------------------------
// Partition: count in-mask rows + init glist to -1, then assign slots.
// ---------------------------------------------------------------------------
__global__ void part_zero_kernel(int* pc) {
    if (threadIdx.x < 4) pc[threadIdx.x] = 0;
}

__global__ void part_count_kernel(const int* __restrict__ mask, int* __restrict__ glist,
                                  int* __restrict__ pc) {
    __shared__ int cnt;
    int tid = threadIdx.x;
    if (tid == 0) cnt = 0;
    __syncthreads();
    int i = blockIdx.x * 256 + tid;
    int m = (i < PN0) ? (mask[i] != 0 ? 1 : 0) : 0;
    unsigned bal = __ballot_sync(0xFFFFFFFFu, m);
    if ((tid & 31) == 0 && bal) atomicAdd(&cnt, __popc(bal));
    if (i < GLIST_LEN) glist[i] = -1;
    __syncthreads();
    if (tid == 0 && cnt) atomicAdd(&pc[0], cnt);
}

__global__ void part_assign_kernel(const int* __restrict__ mask, int* __restrict__ glist,
                                   int* __restrict__ pc) {
    __shared__ int wtot_in[8], wtot_out[8];
    __shared__ int base_in, base_out;
    int tid = threadIdx.x;
    int lane = tid & 31, warp = tid >> 5;
    int i = blockIdx.x * 256 + tid;
    int valid = i < PN0;
    int m = (valid && mask[i] != 0) ? 1 : 0;
    int o = (valid && !m) ? 1 : 0;
    unsigned bin = __ballot_sync(0xFFFFFFFFu, m);
    unsigned bout = __ballot_sync(0xFFFFFFFFu, o);
    int rin = __popc(bin & ((1u << lane) - 1));
    int rout = __popc(bout & ((1u << lane) - 1));
    if (lane == 0) { wtot_in[warp] = __popc(bin); wtot_out[warp] = __popc(bout); }
    __syncthreads();
    if (tid == 0) {
        int ti = 0, to = 0;
#pragma unroll
        for (int w = 0; w < 8; w++) {
            int a = wtot_in[w], b = wtot_out[w];
            wtot_in[w] = ti; wtot_out[w] = to;
            ti += a; to += b;
        }
        base_in = ti ? atomicAdd(&pc[1], ti) : 0;
        base_out = to ? atomicAdd(&pc[2], to) : 0;
    }
    __syncthreads();
    int n_in = pc[0];
    int out_base = (n_in + 127) & ~127;
    if (m) glist[base_in + wtot_in[warp] + rin] = i;
    if (o) glist[out_base + base_out + wtot_out[warp] + rout] = i;
}

// ---------------------------------------------------------------------------
// CSR build kernels
// ---------------------------------------------------------------------------
__global__ void zero4_kernel(int* a, int na, int* b, int nb, int* c, int nc, int* d, int nd) {
    int i = blockIdx.x * blockDim.x + threadIdx.x;
    if (i < na) a[i] = 0;
    if (i < nb) b[i] = 0;
    if (i < nc) c[i] = 0;
    if (i < nd) d[i] = 0;
}

__global__ void hist2_kernel(const int* __restrict__ dst0, int E0, int* __restrict__ cnt0,
                             const int* __restrict__ dst1, int E1, int* __restrict__ cnt1) {
    int i = blockIdx.x * blockDim.x + threadIdx.x;
    if (i < E0) atomicAdd(&cnt0[dst0[i]], 1);
    if (i < E1) atomicAdd(&cnt1[dst1[i]], 1);
}

__device__ void scan_body(const int* __restrict__ cnt, int* __restrict__ rowptr, int n) {
    __shared__ int warp_sums[32];
    __shared__ int s_carry;
    const int tid = threadIdx.x;
    const int lane = tid & 31;
    const int warp = tid >> 5;
    if (tid == 0) { s_carry = 0; rowptr[0] = 0; }
    __syncthreads();

    const int TILE = 4096;
    for (int base = 0; base < n; base += TILE) {
        int i0 = base + tid * 4;
        int4 v = make_int4(0, 0, 0, 0);
        if (i0 + 3 < n) {
            v = *(const int4*)(cnt + i0);
        } else {
            if (i0 + 0 < n) v.x = cnt[i0 + 0];
            if (i0 + 1 < n) v.y = cnt[i0 + 1];
            if (i0 + 2 < n) v.z = cnt[i0 + 2];
        }
        int s1 = v.x, s2 = s1 + v.y, s3 = s2 + v.z, s4 = s3 + v.w;
        int t = s4;
#pragma unroll
        for (int off = 1; off < 32; off <<= 1) {
            int u = __shfl_up_sync(0xFFFFFFFFu, t, off);
            if (lane >= off) t += u;
        }
        if (lane == 31) warp_sums[warp] = t;
        __syncthreads();
        if (warp == 0) {
            int w = warp_sums[lane];
            int tw = w;
#pragma unroll
            for (int off = 1; off < 32; off <<= 1) {
                int u = __shfl_up_sync(0xFFFFFFFFu, tw, off);
                if (lane >= off) tw += u;
            }
            warp_sums[lane] = tw - w;
        }
        __syncthreads();
        int excl = s_carry + warp_sums[warp] + (t - s4);
        if (i0 + 0 < n) rowptr[i0 + 1] = excl + s1;
        if (i0 + 1 < n) rowptr[i0 + 2] = excl + s2;
        if (i0 + 2 < n) rowptr[i0 + 3] = excl + s3;
        if (i0 + 3 < n) rowptr[i0 + 4] = excl + s4;
        __syncthreads();
        if (tid == 1023) s_carry = excl + s4;
    }
}

__global__ void scan2_kernel(const int* c0, int* r0, int n0,
                             const int* c1, int* r1, int n1) {
    if (blockIdx.x == 0) scan_body(c0, r0, n0);
    else scan_body(c1, r1, n1);
}

__global__ void scatter2_kernel(const int* __restrict__ src0, const int* __restrict__ dst0, int E0,
                                const int* __restrict__ rowptr0, int* __restrict__ fill0,
                                int* __restrict__ csr0,
                                const int* __restrict__ src1, const int* __restrict__ dst1, int E1,
                                const int* __restrict__ rowptr1, int* __restrict__ fill1,
                                int* __restrict__ csr1) {
    int i = blockIdx.x * blockDim.x + threadIdx.x;
    if (i < E0) {
        int d = dst0[i];
        int pos = rowptr0[d] + atomicAdd(&fill0[d], 1);
        csr0[pos] = src0[i];
    }
    if (i < E1) {
        int d = dst1[i];
        int pos = rowptr1[d] + atomicAdd(&fill1[d], 1);
        csr1[pos] = src1[i];
    }
}

// ---------------------------------------------------------------------------
// tf32 GEMM, cp.async 3-stage pipeline, ONE __syncthreads per k-tile.
// BM=128, BN=128, BK=32, 256 threads (8 warps 2x4), warp tile 64x32.
// ---------------------------------------------------------------------------
#define TBM 128
#define TBN 128
#define TBK 32
#define AS_STRIDE 36
#define BS_STRIDE 136
#define STAGE_A (TBM * AS_STRIDE)          // 4608 words
#define STAGE_B (TBK * BS_STRIDE)          // 4352 words
#define STAGE_W (STAGE_A + STAGE_B)        // 8960 words
#define GEMM_SMEM_BYTES (3 * STAGE_W * 4)  // 107520 bytes

#define SEG_RESOLVE(kt, Aout, Bout, kload, lda)                                 \
    if ((kt) < K1) { Aout = A1; Bout = B1; kload = (kt); lda = K1; }            \
    else if ((kt) < K1 + K2) { Aout = A2; Bout = B2; kload = (kt) - K1; lda = K2; } \
    else { Aout = A3; Bout = B3; kload = (kt) - K1 - K2; lda = K3; }

#define ASYNC_LOAD(st, kt)                                                      \
    {                                                                           \
        const float *A_, *B_; int kload_, lda_;                                 \
        SEG_RESOLVE(kt, A_, B_, kload_, lda_);                                  \
        uint32_t abase = smem_u32 + (st) * (STAGE_W * 4);                       \
        uint32_t bbase = abase + STAGE_A * 4;                                   \
        _Pragma("unroll")                                                       \
        for (int i = 0; i < 4; i++) {                                           \
            int idx = tid + i * 256;                                            \
            int m = idx >> 3, kq = (idx & 7) * 4;                               \
            int grow = block_row + m;                                           \
            cp16(abase + (m * AS_STRIDE + kq) * 4,                              \
                 A_ + (size_t)grow * lda_ + kload_ + kq, grow < M ? 16 : 0);    \
        }                                                                       \
        _Pragma("unroll")                                                       \
        for (int i = 0; i < 4; i++) {                                           \
            int idx = tid + i * 256;                                            \
            int k = idx >> 5, n4 = (idx & 31) * 4;                              \
            cp16(bbase + (k * BS_STRIDE + n4) * 4,                              \
                 B_ + (size_t)(kload_ + k) * N + block_col + n4, 16);           \
        }                                                                       \
    }

#define T_COMPUTE(Asb, Bsb)                                                     \
    {                                                                           \
        _Pragma("unroll")                                                       \
        for (int ks = 0; ks < 4; ks++) {                                        \
            uint32_t af[4][4], bf[4][2];                                        \
            _Pragma("unroll")                                                   \
            for (int mt = 0; mt < 4; mt++) {                                    \
                int mb = warpM + 16 * mt + qr;                                  \
                int kb = 8 * ks + qc;                                           \
                af[mt][0] = (Asb)[mb * AS_STRIDE + kb];                         \
                af[mt][1] = (Asb)[(mb + 8) * AS_STRIDE + kb];                   \
                af[mt][2] = (Asb)[mb * AS_STRIDE + kb + 4];                     \
                af[mt][3] = (Asb)[(mb + 8) * AS_STRIDE + kb + 4];               \
            }                                                                   \
            _Pragma("unroll")                                                   \
            for (int nt = 0; nt < 4; nt++) {                                    \
                int nb = warpN + 8 * nt + qr;                                   \
                int kb = 8 * ks + qc;                                           \
                bf[nt][0] = (Bsb)[kb * BS_STRIDE + nb];                         \
                bf[nt][1] = (Bsb)[(kb + 4) * BS_STRIDE + nb];                   \
            }                                                                   \
            _Pragma("unroll")                                                   \
            for (int mt = 0; mt < 4; mt++)                                      \
                _Pragma("unroll")                                               \
                for (int nt = 0; nt < 4; nt++)                                  \
                    mma_tf32(acc[mt][nt][0], acc[mt][nt][1],                    \
                             acc[mt][nt][2], acc[mt][nt][3],                    \
                             af[mt][0], af[mt][1], af[mt][2], af[mt][3],        \
                             bf[nt][0], bf[nt][1]);                             \
        }                                                                       \
    }

// 3-stage mainloop, one barrier per tile:
//   iter t: wait(group t done) -> sync -> issue cp(t+2) [+commit always] -> compute(t)
#define T_MAINLOOP3(Ktot)                                                       \
    {                                                                           \
        const int ntile = (Ktot) / TBK;                                         \
        ASYNC_LOAD(0, 0);                                                       \
        CP_COMMIT();                                                            \
        if (ntile > 1) { ASYNC_LOAD(1, TBK); }                                  \
        CP_COMMIT();                                                            \
        for (int t = 0; t < ntile; t++) {                                       \
            CP_WAIT_G1();                                                       \
            __syncthreads();                                                    \
            if (t + 2 < ntile) { ASYNC_LOAD((t + 2) % 3, (t + 2) * TBK); }      \
            CP_COMMIT();                                                        \
            uint32_t* Asb = dynsmem + (t % 3) * STAGE_W;                        \
            uint32_t* Bsb = Asb + STAGE_A;                                      \
            T_COMPUTE(Asb, Bsb);                                                \
        }                                                                       \
    }

#define T_PROLOG()                                                              \
    extern __shared__ uint32_t dynsmem[];                                       \
    const uint32_t smem_u32 = (uint32_t)__cvta_generic_to_shared(dynsmem);      \
    const int tid = threadIdx.x;                                                \
    const int wid = tid >> 5;                                                   \
    const int lane = tid & 31;                                                  \
    const int qr = lane >> 2;                                                   \
    const int qc = lane & 3;                                                    \
    const int warpM = (wid & 1) * 64;                                           \
    const int warpN = (wid >> 1) * 32;                                          \
    float acc[4][4][4];                                                         \
    _Pragma("unroll")                                                           \
    for (int a = 0; a < 4; a++)                                                 \
        _Pragma("unroll")                                                       \
        for (int b = 0; b < 4; b++)                                             \
            _Pragma("unroll")                                                   \
            for (int c = 0; c < 4; c++) acc[a][b][c] = 0.0f;

// Triple-K-segment GEMM. flags: bit0=relu, bit1=addC, bit2=round-to-tf32.
__global__ __launch_bounds__(256, 2)
void gemm3_tf32_kernel(const float* __restrict__ A1, const float* __restrict__ B1, int K1,
                       const float* __restrict__ A2, const float* __restrict__ B2, int K2,
                       const float* __restrict__ A3, const float* __restrict__ B3, int K3,
                       const float* __restrict__ bias, float* __restrict__ C,
                       int M, int N, int flags) {
    const int block_row = blockIdx.y * TBM;
    const int block_col = blockIdx.x * TBN;
    T_PROLOG();
    T_MAINLOOP3(K1 + K2 + K3);

    const bool doRelu = (flags & 1) != 0;
    const bool doAdd = (flags & 2) != 0;
    const bool doRound = (flags & 4) != 0;
#pragma unroll
    for (int mt = 0; mt < 4; mt++) {
        int r0 = block_row + warpM + 16 * mt + qr;
        int r1 = r0 + 8;
#pragma unroll
        for (int nt = 0; nt < 4; nt++) {
            int col = block_col + warpN + 8 * nt + 2 * qc;
            float bx = 0.f, by = 0.f;
            if (bias) { bx = bias[col]; by = bias[col + 1]; }
            float v0 = acc[mt][nt][0] + bx, v1 = acc[mt][nt][1] + by;
            float v2 = acc[mt][nt][2] + bx, v3 = acc[mt][nt][3] + by;
            if (r0 < M) {
                if (doAdd) {
                    float2 c = *(const float2*)(C + (size_t)r0 * N + col);
                    v0 += c.x; v1 += c.y;
                }
                if (doRelu) { v0 = fmaxf(v0, 0.f); v1 = fmaxf(v1, 0.f); }
                if (doRound) { v0 = rnd_tf32(v0); v1 = rnd_tf32(v1); }
                *(float2*)(C + (size_t)r0 * N + col) = make_float2(v0, v1);
            }
            if (r1 < M) {
                if (doAdd) {
                    float2 c = *(const float2*)(C + (size_t)r1 * N + col);
                    v2 += c.x; v3 += c.y;
                }
                if (doRelu) { v2 = fmaxf(v2, 0.f); v3 = fmaxf(v3, 0.f); }
                if (doRound) { v2 = rnd_tf32(v2); v3 = rnd_tf32(v3); }
                *(float2*)(C + (size_t)r1 * N + col) = make_float2(v2, v3);
            }
        }
    }
}

// ---------------------------------------------------------------------------
// Partitioned prompt GEMM: rows gathered via glist (in-rows first, out-rows
// from 128-aligned out_base). Each block is pure in/out -> N=64, exactly the
// needed half. BM=128, BN=64, BK=32, 8 warps (4x2), warp tile 32x32.
// K = 128 fixed. Epilogue: +bias, relu, tf32-round, scatter to hp[glist[r]].
// ---------------------------------------------------------------------------
#define PBS_STRIDE 72
#define PSTAGE_B (TBK * PBS_STRIDE)            // 2304 words
#define PSTAGE_W (STAGE_A + PSTAGE_B)          // 6912 words
#define PROMPT_SMEM_BYTES (3 * PSTAGE_W * 4)   // 82944 bytes

__global__ __launch_bounds__(256, 2)
void prompt_gemm_part_kernel(const float* __restrict__ F,
                             const float* __restrict__ Bi, const float* __restrict__ Bo,
                             const int* __restrict__ glist, const int* __restrict__ pc,
                             const float* __restrict__ b_pin, const float* __restrict__ b_pout,
                             float* __restrict__ hp) {
    extern __shared__ uint32_t dynsmem[];
    const uint32_t smem_u32 = (uint32_t)__cvta_generic_to_shared(dynsmem);
    const int tid = threadIdx.x;
    const int wid = tid >> 5;
    const int lane = tid & 31;
    const int qr = lane >> 2;
    const int qc = lane & 3;
    const int warpM = (wid & 3) * 32;
    const int warpN = (wid >> 2) * 32;
    const int block_row = blockIdx.y * TBM;

    int n_in = pc[0];
    int out_base = (n_in + 127) & ~127;
    bool is_in = block_row < out_base;
    const float* B = is_in ? Bi : Bo;
    const float* bias = is_in ? b_pin : b_pout;

    // Row ids for this thread's A loads (same rows every k-tile).
    int rowid[4];
#pragma unroll
    for (int i = 0; i < 4; i++) {
        int m = (tid >> 3) + 32 * i;
        rowid[i] = glist[block_row + m];
    }

    float acc[2][4][4];
#pragma unroll
    for (int a = 0; a < 2; a++)
#pragma unroll
        for (int b = 0; b < 4; b++)
#pragma unroll
            for (int c = 0; c < 4; c++) acc[a][b][c] = 0.0f;

#define P_ASYNC_LOAD(st, kt)                                                    \
    {                                                                           \
        uint32_t abase = smem_u32 + (st) * (PSTAGE_W * 4);                      \
        uint32_t bbase = abase + STAGE_A * 4;                                   \
        int kq = (tid & 7) * 4;                                                 \
        _Pragma("unroll")                                                       \
        for (int i = 0; i < 4; i++) {                                           \
            int m = (tid >> 3) + 32 * i;                                        \
            cp16(abase + (m * AS_STRIDE + kq) * 4,                              \
                 F + (size_t)rowid[i] * PD_IN + (kt) + kq,                      \
                 rowid[i] >= 0 ? 16 : 0);                                       \
        }                                                                       \
        _Pragma("unroll")                                                       \
        for (int i = 0; i < 2; i++) {                                           \
            int f = tid + i * 256;                                              \
            int k = f >> 4, n4 = (f & 15) * 4;                                  \
            cp16(bbase + (k * PBS_STRIDE + n4) * 4,                             \
                 B + (size_t)((kt) + k) * PD_PROMPT + n4, 16);                  \
        }                                                                       \
    }

    // 3-stage mainloop (ntile = 4)
    const int ntile = PD_IN / TBK;
    P_ASYNC_LOAD(0, 0);
    CP_COMMIT();
    P_ASYNC_LOAD(1, TBK);
    CP_COMMIT();
    for (int t = 0; t < ntile; t++) {
        CP_WAIT_G1();
        __syncthreads();
        if (t + 2 < ntile) { P_ASYNC_LOAD((t + 2) % 3, (t + 2) * TBK); }
        CP_COMMIT();
        uint32_t* Asb = dynsmem + (t % 3) * PSTAGE_W;
        uint32_t* Bsb = Asb + STAGE_A;
#pragma unroll
        for (int ks = 0; ks < 4; ks++) {
            uint32_t af[2][4], bf[4][2];
            int kb = 8 * ks + qc;
#pragma unroll
            for (int mt = 0; mt < 2; mt++) {
                int mb = warpM + 16 * mt + qr;
                af[mt][0] = Asb[mb * AS_STRIDE + kb];
                af[mt][1] = Asb[(mb + 8) * AS_STRIDE + kb];
                af[mt][2] = Asb[mb * AS_STRIDE + kb + 4];
                af[mt][3] = Asb[(mb + 8) * AS_STRIDE + kb + 4];
            }
#pragma unroll
            for (int nt = 0; nt < 4; nt++) {
                int nb = warpN + 8 * nt + qr;
                bf[nt][0] = Bsb[kb * PBS_STRIDE + nb];
                bf[nt][1] = Bsb[(kb + 4) * PBS_STRIDE + nb];
            }
#pragma unroll
            for (int mt = 0; mt < 2; mt++)
#pragma unroll
                for (int nt = 0; nt < 4; nt++)
                    mma_tf32(acc[mt][nt][0], acc[mt][nt][1],
                             acc[mt][nt][2], acc[mt][nt][3],
                             af[mt][0], af[mt][1], af[mt][2], af[mt][3],
                             bf[nt][0], bf[nt][1]);
        }
    }
#undef P_ASYNC_LOAD

    // Epilogue: scatter to hp rows
#pragma unroll
    for (int mt = 0; mt < 2; mt++) {
        int lr = block_row + warpM + 16 * mt + qr;
        int g0 = glist[lr];
        int g1 = glist[lr + 8];
#pragma unroll
        for (int nt = 0; nt < 4; nt++) {
            int col = warpN + 8 * nt + 2 * qc;
            float bx = bias[col], by = bias[col + 1];
            if (g0 >= 0) {
                float2 o = make_float2(rnd_tf32(fmaxf(acc[mt][nt][0] + bx, 0.f)),
                                       rnd_tf32(fmaxf(acc[mt][nt][1] + by, 0.f)));
                *(float2*)(hp + (size_t)g0 * PD_PROMPT + col) = o;
            }
            if (g1 >= 0) {
                float2 o = make_float2(rnd_tf32(fmaxf(acc[mt][nt][2] + bx, 0.f)),
                                       rnd_tf32(fmaxf(acc[mt][nt][3] + by, 0.f)));
                *(float2*)(hp + (size_t)g1 * PD_PROMPT + col) = o;
            }
        }
    }
}

// ---------------------------------------------------------------------------
// Aggregations (tf32-rounded outputs)
// ---------------------------------------------------------------------------
__global__ void agg_F_kernel(const float* __restrict__ F, const int* __restrict__ csr_src,
                             const int* __restrict__ rowptr, float* __restrict__ out) {
    int d = blockIdx.x;
    int col4 = threadIdx.x * 4;
    int s = rowptr[d], e = rowptr[d + 1];
    float4 a = make_float4(0.f, 0.f, 0.f, 0.f);
    int p = s;
    for (; p + 8 <= e; p += 8) {
#pragma unroll
        for (int j = 0; j < 8; j++) {
            int sr = __ldg(&csr_src[p + j]);
            float4 v = *(const float4*)(F + (size_t)sr * PD_IN + col4);
            a.x += v.x; a.y += v.y; a.z += v.z; a.w += v.w;
        }
    }
    for (; p < e; p++) {
        int sr = __ldg(&csr_src[p]);
        float4 v = *(const float4*)(F + (size_t)sr * PD_IN + col4);
        a.x += v.x; a.y += v.y; a.z += v.z; a.w += v.w;
    }
    int deg = e - s;
    float inv = (deg > 0) ? 1.0f / (float)deg : 0.0f;
    a.x = rnd_tf32(a.x * inv); a.y = rnd_tf32(a.y * inv);
    a.z = rnd_tf32(a.z * inv); a.w = rnd_tf32(a.w * inv);
    *(float4*)(out + (size_t)d * PD_CAT + col4) = a;
}

__global__ void agg_HP_kernel(const float* __restrict__ HP, const int* __restrict__ csr_src,
                              const int* __restrict__ rowptr, float* __restrict__ out) {
    int d = blockIdx.x;
    int col2 = threadIdx.x * 2;
    int s = rowptr[d], e = rowptr[d + 1];
    float2 a = make_float2(0.f, 0.f);
    int p = s;
    for (; p + 8 <= e; p += 8) {
#pragma unroll
        for (int j = 0; j < 8; j++) {
            int sr = __ldg(&csr_src[p + j]);
            float2 v = *(const float2*)(HP + (size_t)sr * PD_PROMPT + col2);
            a.x += v.x; a.y += v.y;
        }
    }
    for (; p < e; p++) {
        int sr = __ldg(&csr_src[p]);
        float2 v = *(const float2*)(HP + (size_t)sr * PD_PROMPT + col2);
        a.x += v.x; a.y += v.y;
    }
    int deg = e - s;
    float inv = (deg > 0) ? 1.0f / (float)deg : 0.0f;
    a.x = rnd_tf32(a.x * inv); a.y = rnd_tf32(a.y * inv);
    *(float2*)(out + (size_t)d * PD_CAT + PD_IN + col2) = a;
}

__global__ void agg_kernel(const float* __restrict__ H, const int* __restrict__ csr_src,
                           const int* __restrict__ rowptr, float* __restrict__ out, int C) {
    int d = blockIdx.x;
    int col4 = threadIdx.x * 4;
    int s = rowptr[d], e = rowptr[d + 1];
    float4 a = make_float4(0.f, 0.f, 0.f, 0.f);
    int p = s;
    for (; p + 8 <= e; p += 8) {
#pragma unroll
        for (int j = 0; j < 8; j++) {
            int sr = __ldg(&csr_src[p + j]);
            float4 v = *(const float4*)(H + (size_t)sr * C + col4);
            a.x += v.x; a.y += v.y; a.z += v.z; a.w += v.w;
        }
    }
    for (; p < e; p++) {
        int sr = __ldg(&csr_src[p]);
        float4 v = *(const float4*)(H + (size_t)sr * C + col4);
        a.x += v.x; a.y += v.y; a.z += v.z; a.w += v.w;
    }
    int deg = e - s;
    float inv = (deg > 0) ? 1.0f / (float)deg : 0.0f;
    a.x = rnd_tf32(a.x * inv); a.y = rnd_tf32(a.y * inv);
    a.z = rnd_tf32(a.z * inv); a.w = rnd_tf32(a.w * inv);
    *(float4*)(out + (size_t)d * C + col4) = a;
}

// ---------------------------------------------------------------------------
// Classifier
// ---------------------------------------------------------------------------
__global__ void cls_kernel(const float* __restrict__ H2, const float* __restrict__ Wc,
                           const float* __restrict__ bc, float* __restrict__ out, int n) {
    int gwarp = (blockIdx.x * blockDim.x + threadIdx.x) >> 5;
    int lane = threadIdx.x & 31;
    if (gwarp >= n) return;
    const float* row = H2 + (size_t)gwarp * PD_HID;
    float c0 = 0.f, c1 = 0.f;
#pragma unroll
    for (int k = lane; k < PD_HID; k += 32) {
        float v = row[k];
        c0 += v * Wc[k * 2 + 0];
        c1 += v * Wc[k * 2 + 1];
    }
#pragma unroll
    for (int off = 16; off; off >>= 1) {
        c0 += __shfl_down_sync(0xFFFFFFFFu, c0, off);
        c1 += __shfl_down_sync(0xFFFFFFFFu, c1, off);
    }
    if (lane == 0) {
        out[gwarp * 2 + 0] = c0 + bc[0];
        out[gwarp * 2 + 1] = c1 + bc[1];
    }
}

// ---------------------------------------------------------------------------
// Launch
// ---------------------------------------------------------------------------
static void* symaddr(const void* sym) {
    void* p = nullptr;
    cudaGetSymbolAddress(&p, sym);
    return p;
}

extern "C" void kernel_launch(void* const* d_in, const int* in_sizes, int n_in_args,
                              void* d_out, int out_size) {
    const float* features = (const float*)d_in[0];
    const int* mask       = (const int*)d_in[1];
    const int* src0       = (const int*)d_in[2];
    const int* dst0       = (const int*)d_in[3];
    const int* src1       = (const int*)d_in[4];
    const int* dst1       = (const int*)d_in[5];
    // d_in[6] = output_nodes_indices (unused by reference)
    const float* w_pin    = (const float*)d_in[7];
    const float* b_pin    = (const float*)d_in[8];
    const float* w_pout   = (const float*)d_in[9];
    const float* b_pout   = (const float*)d_in[10];
    const float* w_self0  = (const float*)d_in[11];
    const float* w_neigh0 = (const float*)d_in[12];
    const float* b0       = (const float*)d_in[13];
    const float* w_self1  = (const float*)d_in[14];
    const float* w_neigh1 = (const float*)d_in[15];
    const float* b1       = (const float*)d_in[16];
    const float* w_cls    = (const float*)d_in[17];
    const float* b_cls    = (const float*)d_in[18];
    float* out = (float*)d_out;

    float* hp   = (float*)symaddr(g_hp);
    float* agg0 = (float*)symaddr(g_agg0);
    float* h1   = (float*)symaddr(g_h1);
    float* agg1 = (float*)symaddr(g_agg1);
    float* h2   = (float*)symaddr(g_h2);
    float* wpi  = (float*)symaddr(g_wpi);
    float* wpo  = (float*)symaddr(g_wpo);
    float* ws0  = (float*)symaddr(g_ws0);
    float* wn0  = (float*)symaddr(g_wn0);
    float* ws1  = (float*)symaddr(g_ws1);
    float* wn1  = (float*)symaddr(g_wn1);
    int* glist   = (int*)symaddr(g_glist);
    int* pc      = (int*)symaddr(g_pc);
    int* cnt0    = (int*)symaddr(g_cnt0);
    int* fill0   = (int*)symaddr(g_fill0);
    int* rowptr0 = (int*)symaddr(g_rowptr0);
    int* cnt1    = (int*)symaddr(g_cnt1);
    int* fill1   = (int*)symaddr(g_fill1);
    int* rowptr1 = (int*)symaddr(g_rowptr1);
    int* csr0    = (int*)symaddr(g_csr0);
    int* csr1    = (int*)symaddr(g_csr1);

    cudaFuncSetAttribute(gemm3_tf32_kernel,
                         cudaFuncAttributeMaxDynamicSharedMemorySize, GEMM_SMEM_BYTES);
    cudaFuncSetAttribute(prompt_gemm_part_kernel,
                         cudaFuncAttributeMaxDynamicSharedMemorySize, PROMPT_SMEM_BYTES);

    cudaStream_t s0 = 0;
    cudaStream_t s1 = g_res.s1;
    cudaStream_t s2 = g_res.s2;

    cudaEventRecord(g_res.ev_start, s0);
    cudaStreamWaitEvent(s1, g_res.ev_start, 0);
    cudaStreamWaitEvent(s2, g_res.ev_start, 0);

    // s1: CSR build chain
    zero4_kernel<<<(PN1 + 255) / 256, 256, 0, s1>>>(cnt0, PN1, fill0, PN1, cnt1, PN2, fill1, PN2);
    hist2_kernel<<<(PE0 + 255) / 256, 256, 0, s1>>>(dst0, PE0, cnt0, dst1, PE1, cnt1);
    scan2_kernel<<<2, 1024, 0, s1>>>(cnt0, rowptr0, PN1, cnt1, rowptr1, PN2);
    scatter2_kernel<<<(PE0 + 255) / 256, 256, 0, s1>>>(src0, dst0, PE0, rowptr0, fill0, csr0,
                                                       src1, dst1, PE1, rowptr1, fill1, csr1);
    cudaEventRecord(g_res.ev_csr, s1);

    // s0: partition + weight rounding, then partitioned prompt GEMM
    part_zero_kernel<<<1, 32, 0, s0>>>(pc);
    part_count_kernel<<<(GLIST_LEN + 255) / 256, 256, 0, s0>>>(mask, glist, pc);
    part_assign_kernel<<<(PN0 + 255) / 256, 256, 0, s0>>>(mask, glist, pc);
    round_weights_kernel<<<(384 * 256 + 255) / 256, 256, 0, s0>>>(
        w_pin, w_pout, w_self0, w_neigh0, w_self1, w_neigh1, wpi, wpo, ws0, wn0, ws1, wn1);
    {
        dim3 grid(1, GLIST_LEN / TBM);  // 1564 tiles over the padded list
        prompt_gemm_part_kernel<<<grid, 256, PROMPT_SMEM_BYTES, s0>>>(
            features, wpi, wpo, glist, pc, b_pin, b_pout, hp);
    }
    cudaEventRecord(g_res.ev_hp, s0);

    // s2: F-part aggregation (CSR only) — overlaps prompt GEMM.
    cudaStreamWaitEvent(s2, g_res.ev_csr, 0);
    agg_F_kernel<<<PN1, 32, 0, s2>>>(features, csr0, rowptr0, agg0);
    cudaEventRecord(g_res.ev_aggF, s2);

    // s1: self-GEMM layer 0: h1 = [F|hp]@ws0 + b0
    cudaStreamWaitEvent(s1, g_res.ev_hp, 0);
    {
        dim3 grid(PD_HID / TBN, (PN1 + TBM - 1) / TBM);
        gemm3_tf32_kernel<<<grid, 256, GEMM_SMEM_BYTES, s1>>>(
            features, ws0, PD_IN,
            hp, ws0 + (size_t)PD_IN * PD_HID, PD_PROMPT,
            nullptr, nullptr, 0,
            b0, h1, PN1, PD_HID, /*flags=*/0);
    }
    cudaEventRecord(g_res.ev_self0, s1);

    // s0: hp-part aggregation
    cudaStreamWaitEvent(s0, g_res.ev_csr, 0);
    agg_HP_kernel<<<PN1, 32, 0, s0>>>(hp, csr0, rowptr0, agg0);

    // s0: neigh-GEMM layer 0: h1 = round(relu(agg0@wn0 + h1))
    cudaStreamWaitEvent(s0, g_res.ev_aggF, 0);
    cudaStreamWaitEvent(s0, g_res.ev_self0, 0);
    {
        dim3 grid(PD_HID / TBN, (PN1 + TBM - 1) / TBM);
        gemm3_tf32_kernel<<<grid, 256, GEMM_SMEM_BYTES, s0>>>(
            agg0, wn0, PD_CAT,
            nullptr, nullptr, 0, nullptr, nullptr, 0,
            nullptr, h1, PN1, PD_HID, /*flags=*/7);  // addC + relu + round
    }
    cudaEventRecord(g_res.ev_h1, s0);

    // s1: self-GEMM layer 1: h2 = h1@ws1 + b1
    cudaStreamWaitEvent(s1, g_res.ev_h1, 0);
    {
        dim3 grid(PD_HID / TBN, (PN2 + TBM - 1) / TBM);
        gemm3_tf32_kernel<<<grid, 256, GEMM_SMEM_BYTES, s1>>>(
            h1, ws1, PD_HID,
            nullptr, nullptr, 0, nullptr, nullptr, 0,
            b1, h2, PN2, PD_HID, /*flags=*/0);
    }
    cudaEventRecord(g_res.ev_self1, s1);

    // s0: aggregation layer 1
    agg_kernel<<<PN2, PD_HID / 4, 0, s0>>>(h1, csr1, rowptr1, agg1, PD_HID);

    // s0: neigh-GEMM layer 1: h2 = agg1@wn1 + h2
    cudaStreamWaitEvent(s0, g_res.ev_self1, 0);
    {
        dim3 grid(PD_HID / TBN, (PN2 + TBM - 1) / TBM);
        gemm3_tf32_kernel<<<grid, 256, GEMM_SMEM_BYTES, s0>>>(
            agg1, wn1, PD_HID,
            nullptr, nullptr, 0, nullptr, nullptr, 0,
            nullptr, h2, PN2, PD_HID, /*flags=*/2);  // addC
    }

    // Classifier
    cls_kernel<<<(PN2 * 32 + 255) / 256, 256, 0, s0>>>(h2, w_cls, b_cls, out, PN2);
}